// round 2
// baseline (speedup 1.0000x reference)
#include <cuda_runtime.h>

#define CD 1024
#define BD 4
#define TD 2048
#define NH 16
#define HD 64
#define MD (BD*TD)   // 8192 rows

// Scratch (allocation-free rule: __device__ globals). 4 x 32MB.
__device__ float g_q[(size_t)MD * CD];
__device__ float g_k[(size_t)MD * CD];
__device__ float g_v[(size_t)MD * CD];
__device__ float g_att[(size_t)MD * CD];

// ---------------------------------------------------------------------------
// GEMM: out[m,n] = sum_k A[m,k] * W[n,k]   (A: [M,1024], W: [1024,1024])
// Block tile 128x128, BK=16, 256 threads, 8x8 register micro-tile.
// Smem stored transposed [kk][m] with +4 pad (row stride 132 floats = 16B
// multiple) so compute reads are LDS.128.
// ---------------------------------------------------------------------------
__global__ void __launch_bounds__(256, 2) gemm_xwt(const float* __restrict__ A,
                                                   const float* __restrict__ W,
                                                   float* __restrict__ out) {
    __shared__ __align__(16) float As[16][132];
    __shared__ __align__(16) float Bs[16][132];
    const int tid = threadIdx.x;
    const int tx = tid & 15, ty = tid >> 4;
    const int m0 = blockIdx.y * 128;
    const int n0 = blockIdx.x * 128;

    float acc[8][8];
    #pragma unroll
    for (int i = 0; i < 8; i++)
        #pragma unroll
        for (int j = 0; j < 8; j++) acc[i][j] = 0.f;

    for (int k0 = 0; k0 < CD; k0 += 16) {
        #pragma unroll
        for (int i = tid; i < 128 * 16; i += 256) {
            int m = i >> 4, kk = i & 15;
            As[kk][m] = A[(size_t)(m0 + m) * CD + k0 + kk];
            Bs[kk][m] = W[(size_t)(n0 + m) * CD + k0 + kk];
        }
        __syncthreads();
        #pragma unroll
        for (int kk = 0; kk < 16; kk++) {
            float4 a0 = *(const float4*)&As[kk][ty * 8];
            float4 a1 = *(const float4*)&As[kk][ty * 8 + 4];
            float4 b0 = *(const float4*)&Bs[kk][tx * 8];
            float4 b1 = *(const float4*)&Bs[kk][tx * 8 + 4];
            float a[8] = {a0.x, a0.y, a0.z, a0.w, a1.x, a1.y, a1.z, a1.w};
            float b[8] = {b0.x, b0.y, b0.z, b0.w, b1.x, b1.y, b1.z, b1.w};
            #pragma unroll
            for (int i = 0; i < 8; i++)
                #pragma unroll
                for (int j = 0; j < 8; j++)
                    acc[i][j] = fmaf(a[i], b[j], acc[i][j]);
        }
        __syncthreads();
    }
    #pragma unroll
    for (int i = 0; i < 8; i++) {
        size_t row = (size_t)(m0 + ty * 8 + i) * CD + n0;
        #pragma unroll
        for (int j = 0; j < 8; j += 4) {
            float4 v = make_float4(acc[i][j], acc[i][j + 1], acc[i][j + 2], acc[i][j + 3]);
            *(float4*)&out[row + tx * 8 + j] = v;
        }
    }
}

// ---------------------------------------------------------------------------
// Flash attention (causal), fp32. One CTA = one (b,h) x 64-query block.
// 256 threads as 16(tx) x 16(ty). Thread owns 4 q-rows (ty*4+i) and 4
// strided cols (tx + 16*j)  -> all inner-loop LDS bank-conflict-free.
// Row softmax reductions via shfl.xor over the 16 tx lanes (half-warp).
// Smem: Qs[64][65], KP[64][65] (K tile, reused for P tile), Vs[64][64].
// ---------------------------------------------------------------------------
#define ATTN_SMEM ((2 * 64 * 65 + 64 * 64) * 4)   // 49664 bytes

__global__ void __launch_bounds__(256, 1) attn_kernel(const float* __restrict__ Q,
                                                      const float* __restrict__ K,
                                                      const float* __restrict__ V,
                                                      float* __restrict__ O) {
    extern __shared__ float sm[];
    float (*Qs)[65] = (float (*)[65])sm;                 // [q][d]
    float (*KP)[65] = (float (*)[65])(sm + 64 * 65);     // K:[c][d] then P:[q][c]
    float (*Vs)[64] = (float (*)[64])(sm + 2 * 64 * 65); // [c][d]

    const int tid = threadIdx.x;
    const int tx = tid & 15, ty = tid >> 4;
    const int b = blockIdx.y >> 4, h = blockIdx.y & 15;
    const int i0 = blockIdx.x * 64;
    const size_t base = ((size_t)b * TD) * CD + (size_t)h * HD;

    for (int i = tid; i < 64 * 64; i += 256) {
        int q = i >> 6, d = i & 63;
        Qs[q][d] = Q[base + (size_t)(i0 + q) * CD + d];
    }

    float m_i[4], l_i[4], o[4][4];
    #pragma unroll
    for (int i = 0; i < 4; i++) {
        m_i[i] = -1e30f;
        l_i[i] = 0.f;
        #pragma unroll
        for (int j = 0; j < 4; j++) o[i][j] = 0.f;
    }

    for (int j0 = 0; j0 <= i0; j0 += 64) {
        for (int i = tid; i < 64 * 64; i += 256) {
            int c = i >> 6, d = i & 63;
            size_t g = base + (size_t)(j0 + c) * CD + d;
            KP[c][d] = K[g];
            Vs[c][d] = V[g];
        }
        __syncthreads();

        // S = Q K^T (over d)
        float s[4][4];
        #pragma unroll
        for (int i = 0; i < 4; i++)
            #pragma unroll
            for (int j = 0; j < 4; j++) s[i][j] = 0.f;

        #pragma unroll
        for (int d = 0; d < 64; d++) {
            float a[4], bb[4];
            #pragma unroll
            for (int i = 0; i < 4; i++) a[i] = Qs[ty * 4 + i][d];
            #pragma unroll
            for (int j = 0; j < 4; j++) bb[j] = KP[tx + 16 * j][d];
            #pragma unroll
            for (int i = 0; i < 4; i++)
                #pragma unroll
                for (int j = 0; j < 4; j++)
                    s[i][j] = fmaf(a[i], bb[j], s[i][j]);
        }

        // scale + causal mask
        const bool diag = (j0 == i0);
        #pragma unroll
        for (int i = 0; i < 4; i++) {
            int row = ty * 4 + i;
            #pragma unroll
            for (int j = 0; j < 4; j++) {
                int col = tx + 16 * j;
                float sv = s[i][j] * 0.125f;
                if (diag && col > row) sv = -1e30f;
                s[i][j] = sv;
            }
        }

        // online softmax update (per row, reduced across the 16 tx lanes)
        #pragma unroll
        for (int i = 0; i < 4; i++) {
            float rm = fmaxf(fmaxf(s[i][0], s[i][1]), fmaxf(s[i][2], s[i][3]));
            #pragma unroll
            for (int ms = 1; ms < 16; ms <<= 1)
                rm = fmaxf(rm, __shfl_xor_sync(0xffffffffu, rm, ms));
            float mnew = fmaxf(m_i[i], rm);
            float corr = __expf(m_i[i] - mnew);
            float rs = 0.f;
            #pragma unroll
            for (int j = 0; j < 4; j++) {
                s[i][j] = __expf(s[i][j] - mnew);
                rs += s[i][j];
            }
            #pragma unroll
            for (int ms = 1; ms < 16; ms <<= 1)
                rs += __shfl_xor_sync(0xffffffffu, rs, ms);
            l_i[i] = l_i[i] * corr + rs;
            m_i[i] = mnew;
            #pragma unroll
            for (int j = 0; j < 4; j++) o[i][j] *= corr;
        }
        __syncthreads();   // all warps done reading K tile from KP

        // P -> smem
        #pragma unroll
        for (int i = 0; i < 4; i++)
            #pragma unroll
            for (int j = 0; j < 4; j++)
                KP[ty * 4 + i][tx + 16 * j] = s[i][j];
        __syncthreads();

        // O += P V
        #pragma unroll
        for (int c = 0; c < 64; c++) {
            float p[4], vv[4];
            #pragma unroll
            for (int i = 0; i < 4; i++) p[i] = KP[ty * 4 + i][c];
            #pragma unroll
            for (int j = 0; j < 4; j++) vv[j] = Vs[c][tx + 16 * j];
            #pragma unroll
            for (int i = 0; i < 4; i++)
                #pragma unroll
                for (int j = 0; j < 4; j++)
                    o[i][j] = fmaf(p[i], vv[j], o[i][j]);
        }
        __syncthreads();
    }

    #pragma unroll
    for (int i = 0; i < 4; i++) {
        float inv = 1.0f / l_i[i];
        size_t row = base + (size_t)(i0 + ty * 4 + i) * CD;
        #pragma unroll
        for (int j = 0; j < 4; j++)
            O[row + tx + 16 * j] = o[i][j] * inv;
    }
}

// ---------------------------------------------------------------------------

extern "C" void kernel_launch(void* const* d_in, const int* in_sizes, int n_in,
                              void* d_out, int out_size) {
    const float* x  = (const float*)d_in[0];
    const float* Wq = (const float*)d_in[1];
    const float* Wk = (const float*)d_in[2];
    const float* Wv = (const float*)d_in[3];
    const float* Wo = (const float*)d_in[4];
    float* out = (float*)d_out;

    float *pq, *pk, *pv, *pa;
    cudaGetSymbolAddress((void**)&pq, g_q);
    cudaGetSymbolAddress((void**)&pk, g_k);
    cudaGetSymbolAddress((void**)&pv, g_v);
    cudaGetSymbolAddress((void**)&pa, g_att);

    cudaFuncSetAttribute(attn_kernel, cudaFuncAttributeMaxDynamicSharedMemorySize,
                         ATTN_SMEM);

    dim3 ggrid(CD / 128, MD / 128);   // (8, 64)
    gemm_xwt<<<ggrid, 256>>>(x, Wq, pq);
    gemm_xwt<<<ggrid, 256>>>(x, Wk, pk);
    gemm_xwt<<<ggrid, 256>>>(x, Wv, pv);
    attn_kernel<<<dim3(TD / 64, BD * NH), 256, ATTN_SMEM>>>(pq, pk, pv, pa);
    gemm_xwt<<<ggrid, 256>>>(pa, Wo, out);
}

// round 3
// speedup vs baseline: 1.8474x; 1.8474x over previous
#include <cuda_runtime.h>
#include <cuda_bf16.h>
#include <cstdint>

#define CD 1024
#define BD 4
#define TD 2048
#define NH 16
#define HD 64
#define MD (BD*TD)   // 8192 rows

// Scratch (__device__ globals; allocation-free rule).
__device__ float g_q[(size_t)MD * CD];
__device__ float g_k[(size_t)MD * CD];
__device__ float g_v[(size_t)MD * CD];
__device__ float g_att[(size_t)MD * CD];
__device__ __nv_bfloat16 g_xh[(size_t)MD * CD];
__device__ __nv_bfloat16 g_xl[(size_t)MD * CD];
__device__ __nv_bfloat16 g_ah[(size_t)MD * CD];
__device__ __nv_bfloat16 g_al[(size_t)MD * CD];
__device__ __nv_bfloat16 g_wh[4ull * CD * CD];
__device__ __nv_bfloat16 g_wl[4ull * CD * CD];

// ---------------------------------------------------------------------------
// fp32 -> (bf16 hi, bf16 lo) split.  hi = rn(a), lo = rn(a - hi).
// ---------------------------------------------------------------------------
__global__ void split_kernel(const float* __restrict__ in,
                             __nv_bfloat16* __restrict__ hi,
                             __nv_bfloat16* __restrict__ lo, int n4) {
    int i = blockIdx.x * blockDim.x + threadIdx.x;
    if (i >= n4) return;
    float4 v = ((const float4*)in)[i];
    __nv_bfloat16 h0 = __float2bfloat16_rn(v.x);
    __nv_bfloat16 h1 = __float2bfloat16_rn(v.y);
    __nv_bfloat16 h2 = __float2bfloat16_rn(v.z);
    __nv_bfloat16 h3 = __float2bfloat16_rn(v.w);
    __nv_bfloat16 l0 = __float2bfloat16_rn(v.x - __bfloat162float(h0));
    __nv_bfloat16 l1 = __float2bfloat16_rn(v.y - __bfloat162float(h1));
    __nv_bfloat16 l2 = __float2bfloat16_rn(v.z - __bfloat162float(h2));
    __nv_bfloat16 l3 = __float2bfloat16_rn(v.w - __bfloat162float(h3));
    ((__nv_bfloat162*)hi)[2 * i]     = __halves2bfloat162(h0, h1);
    ((__nv_bfloat162*)hi)[2 * i + 1] = __halves2bfloat162(h2, h3);
    ((__nv_bfloat162*)lo)[2 * i]     = __halves2bfloat162(l0, l1);
    ((__nv_bfloat162*)lo)[2 * i + 1] = __halves2bfloat162(l2, l3);
}

// ---------------------------------------------------------------------------
// Tensor-core GEMM: C[m,n] = sum_k A[m,k] * W[n,k], fp32-accurate via
// 2-term bf16 split (3 HMMAs per logical MMA).
// CTA tile 128x128x32, 8 warps (warp tile 32x64), cp.async double buffer.
// smem row stride 40 halves (80B) -> conflict-free ldmatrix phases.
// ---------------------------------------------------------------------------
#define GBM 128
#define GBN 128
#define GBK 32
#define TSTRIDE 40
#define TILE_H (128 * TSTRIDE)     // halves per tile
#define STAGE_H (4 * TILE_H)       // Ah, Al, Wh, Wl
#define GSMEM (2 * STAGE_H * 2)    // bytes = 81920

__device__ __forceinline__ void cp_async16(uint32_t s, const void* g) {
    asm volatile("cp.async.cg.shared.global [%0], [%1], 16;\n" :: "r"(s), "l"(g));
}
__device__ __forceinline__ void cp_commit() {
    asm volatile("cp.async.commit_group;\n");
}
__device__ __forceinline__ void cp_wait0() {
    asm volatile("cp.async.wait_group 0;\n");
}
__device__ __forceinline__ void ldsm4(uint32_t* r, uint32_t a) {
    asm volatile("ldmatrix.sync.aligned.m8n8.x4.shared.b16 {%0,%1,%2,%3}, [%4];\n"
                 : "=r"(r[0]), "=r"(r[1]), "=r"(r[2]), "=r"(r[3]) : "r"(a));
}
__device__ __forceinline__ void mma16816(float* c, const uint32_t* a,
                                         uint32_t b0, uint32_t b1) {
    asm volatile(
        "mma.sync.aligned.m16n8k16.row.col.f32.bf16.bf16.f32 "
        "{%0,%1,%2,%3},{%4,%5,%6,%7},{%8,%9},{%0,%1,%2,%3};\n"
        : "+f"(c[0]), "+f"(c[1]), "+f"(c[2]), "+f"(c[3])
        : "r"(a[0]), "r"(a[1]), "r"(a[2]), "r"(a[3]), "r"(b0), "r"(b1));
}

__global__ void __launch_bounds__(256) gemm_bf16x2(
    const __nv_bfloat16* __restrict__ Ah, const __nv_bfloat16* __restrict__ Al,
    const __nv_bfloat16* __restrict__ Wh, const __nv_bfloat16* __restrict__ Wl,
    float* __restrict__ C) {
    extern __shared__ __align__(16) __nv_bfloat16 sm_g[];
    const uint32_t sbase = (uint32_t)__cvta_generic_to_shared(sm_g);
    const int tid = threadIdx.x;
    const int lane = tid & 31, warp = tid >> 5;
    const int wm = warp >> 1, wn = warp & 1;   // 4 x 2 warps
    const int m0 = blockIdx.y * GBM;
    const int n0 = blockIdx.x * GBN;

    // staging indices: thread loads 16B chunks; row=tid/4 (and +64), chunk=tid%4
    const int lrow = tid >> 2;
    const int lch = (tid & 3) * 8;   // halves
    const __nv_bfloat16* gp[4] = {
        Ah + (size_t)(m0 + lrow) * CD + lch,
        Al + (size_t)(m0 + lrow) * CD + lch,
        Wh + (size_t)(n0 + lrow) * CD + lch,
        Wl + (size_t)(n0 + lrow) * CD + lch};
    const uint32_t s_off = (uint32_t)(lrow * TSTRIDE + lch) * 2;

    // fragment lane offsets
    const int lrow_a = (lane & 7) + ((lane >> 3) & 1) * 8;
    const int kca = (lane >> 4) * 8;
    const int lrow_b = (lane & 7) + (lane >> 4) * 8;
    const int kcb = ((lane >> 3) & 1) * 8;

    float acc[2][8][4];
    #pragma unroll
    for (int i = 0; i < 2; i++)
        #pragma unroll
        for (int j = 0; j < 8; j++)
            #pragma unroll
            for (int q = 0; q < 4; q++) acc[i][j][q] = 0.f;

    auto load_stage = [&](int s, int k0) {
        uint32_t so = sbase + (uint32_t)(s * STAGE_H) * 2;
        #pragma unroll
        for (int t = 0; t < 4; t++) {
            const __nv_bfloat16* g = gp[t] + k0;
            uint32_t sa = so + (uint32_t)(t * TILE_H) * 2 + s_off;
            cp_async16(sa, g);
            cp_async16(sa + 64 * TSTRIDE * 2, g + (size_t)64 * CD);
        }
    };

    load_stage(0, 0);
    cp_commit();

    const int NIT = CD / GBK;   // 32
    for (int it = 0; it < NIT; it++) {
        cp_wait0();
        __syncthreads();
        if (it + 1 < NIT) {
            load_stage((it + 1) & 1, (it + 1) * GBK);
            cp_commit();
        }
        uint32_t so = sbase + (uint32_t)((it & 1) * STAGE_H) * 2;
        #pragma unroll
        for (int ks = 0; ks < 2; ks++) {
            const int k0h = ks * 16;
            uint32_t ah[2][4], al[2][4];
            #pragma unroll
            for (int mt = 0; mt < 2; mt++) {
                int row = wm * 32 + mt * 16 + lrow_a;
                uint32_t a = so + (uint32_t)(row * TSTRIDE + k0h + kca) * 2;
                ldsm4(ah[mt], a);
                ldsm4(al[mt], a + TILE_H * 2);
            }
            uint32_t bh[4][4], bl[4][4];
            #pragma unroll
            for (int j = 0; j < 4; j++) {
                int nr = wn * 64 + j * 16 + lrow_b;
                uint32_t a = so + (uint32_t)(2 * TILE_H + nr * TSTRIDE + k0h + kcb) * 2;
                ldsm4(bh[j], a);
                ldsm4(bl[j], a + TILE_H * 2);
            }
            #pragma unroll
            for (int mt = 0; mt < 2; mt++)
                #pragma unroll
                for (int j = 0; j < 4; j++) {
                    mma16816(acc[mt][2 * j],     ah[mt], bh[j][0], bh[j][1]);
                    mma16816(acc[mt][2 * j],     ah[mt], bl[j][0], bl[j][1]);
                    mma16816(acc[mt][2 * j],     al[mt], bh[j][0], bh[j][1]);
                    mma16816(acc[mt][2 * j + 1], ah[mt], bh[j][2], bh[j][3]);
                    mma16816(acc[mt][2 * j + 1], ah[mt], bl[j][2], bl[j][3]);
                    mma16816(acc[mt][2 * j + 1], al[mt], bh[j][2], bh[j][3]);
                }
        }
    }

    // epilogue: c0,c1 = (row, col..col+1); c2,c3 = (row+8, ...)
    const int cr = lane >> 2, cc = (lane & 3) * 2;
    #pragma unroll
    for (int mt = 0; mt < 2; mt++) {
        int r = m0 + wm * 32 + mt * 16 + cr;
        #pragma unroll
        for (int nt = 0; nt < 8; nt++) {
            int col = n0 + wn * 64 + nt * 8 + cc;
            float2 v0 = make_float2(acc[mt][nt][0], acc[mt][nt][1]);
            float2 v1 = make_float2(acc[mt][nt][2], acc[mt][nt][3]);
            *(float2*)&C[(size_t)r * CD + col] = v0;
            *(float2*)&C[(size_t)(r + 8) * CD + col] = v1;
        }
    }
}

// ---------------------------------------------------------------------------
// Flash attention (causal), fp32 — unchanged from Round 1 (Round 3 target).
// ---------------------------------------------------------------------------
#define ATTN_SMEM ((2 * 64 * 65 + 64 * 64) * 4)

__global__ void __launch_bounds__(256, 1) attn_kernel(const float* __restrict__ Q,
                                                      const float* __restrict__ K,
                                                      const float* __restrict__ V,
                                                      float* __restrict__ O) {
    extern __shared__ float sm[];
    float (*Qs)[65] = (float (*)[65])sm;
    float (*KP)[65] = (float (*)[65])(sm + 64 * 65);
    float (*Vs)[64] = (float (*)[64])(sm + 2 * 64 * 65);

    const int tid = threadIdx.x;
    const int tx = tid & 15, ty = tid >> 4;
    const int b = blockIdx.y >> 4, h = blockIdx.y & 15;
    const int i0 = blockIdx.x * 64;
    const size_t base = ((size_t)b * TD) * CD + (size_t)h * HD;

    for (int i = tid; i < 64 * 64; i += 256) {
        int q = i >> 6, d = i & 63;
        Qs[q][d] = Q[base + (size_t)(i0 + q) * CD + d];
    }

    float m_i[4], l_i[4], o[4][4];
    #pragma unroll
    for (int i = 0; i < 4; i++) {
        m_i[i] = -1e30f;
        l_i[i] = 0.f;
        #pragma unroll
        for (int j = 0; j < 4; j++) o[i][j] = 0.f;
    }

    for (int j0 = 0; j0 <= i0; j0 += 64) {
        for (int i = tid; i < 64 * 64; i += 256) {
            int c = i >> 6, d = i & 63;
            size_t g = base + (size_t)(j0 + c) * CD + d;
            KP[c][d] = K[g];
            Vs[c][d] = V[g];
        }
        __syncthreads();

        float s[4][4];
        #pragma unroll
        for (int i = 0; i < 4; i++)
            #pragma unroll
            for (int j = 0; j < 4; j++) s[i][j] = 0.f;

        #pragma unroll
        for (int d = 0; d < 64; d++) {
            float a[4], bb[4];
            #pragma unroll
            for (int i = 0; i < 4; i++) a[i] = Qs[ty * 4 + i][d];
            #pragma unroll
            for (int j = 0; j < 4; j++) bb[j] = KP[tx + 16 * j][d];
            #pragma unroll
            for (int i = 0; i < 4; i++)
                #pragma unroll
                for (int j = 0; j < 4; j++)
                    s[i][j] = fmaf(a[i], bb[j], s[i][j]);
        }

        const bool diag = (j0 == i0);
        #pragma unroll
        for (int i = 0; i < 4; i++) {
            int row = ty * 4 + i;
            #pragma unroll
            for (int j = 0; j < 4; j++) {
                int col = tx + 16 * j;
                float sv = s[i][j] * 0.125f;
                if (diag && col > row) sv = -1e30f;
                s[i][j] = sv;
            }
        }

        #pragma unroll
        for (int i = 0; i < 4; i++) {
            float rm = fmaxf(fmaxf(s[i][0], s[i][1]), fmaxf(s[i][2], s[i][3]));
            #pragma unroll
            for (int ms = 1; ms < 16; ms <<= 1)
                rm = fmaxf(rm, __shfl_xor_sync(0xffffffffu, rm, ms));
            float mnew = fmaxf(m_i[i], rm);
            float corr = __expf(m_i[i] - mnew);
            float rs = 0.f;
            #pragma unroll
            for (int j = 0; j < 4; j++) {
                s[i][j] = __expf(s[i][j] - mnew);
                rs += s[i][j];
            }
            #pragma unroll
            for (int ms = 1; ms < 16; ms <<= 1)
                rs += __shfl_xor_sync(0xffffffffu, rs, ms);
            l_i[i] = l_i[i] * corr + rs;
            m_i[i] = mnew;
            #pragma unroll
            for (int j = 0; j < 4; j++) o[i][j] *= corr;
        }
        __syncthreads();

        #pragma unroll
        for (int i = 0; i < 4; i++)
            #pragma unroll
            for (int j = 0; j < 4; j++)
                KP[ty * 4 + i][tx + 16 * j] = s[i][j];
        __syncthreads();

        #pragma unroll
        for (int c = 0; c < 64; c++) {
            float p[4], vv[4];
            #pragma unroll
            for (int i = 0; i < 4; i++) p[i] = KP[ty * 4 + i][c];
            #pragma unroll
            for (int j = 0; j < 4; j++) vv[j] = Vs[c][tx + 16 * j];
            #pragma unroll
            for (int i = 0; i < 4; i++)
                #pragma unroll
                for (int j = 0; j < 4; j++)
                    o[i][j] = fmaf(p[i], vv[j], o[i][j]);
        }
        __syncthreads();
    }

    #pragma unroll
    for (int i = 0; i < 4; i++) {
        float inv = 1.0f / l_i[i];
        size_t row = base + (size_t)(i0 + ty * 4 + i) * CD;
        #pragma unroll
        for (int j = 0; j < 4; j++)
            O[row + tx + 16 * j] = o[i][j] * inv;
    }
}

// ---------------------------------------------------------------------------

extern "C" void kernel_launch(void* const* d_in, const int* in_sizes, int n_in,
                              void* d_out, int out_size) {
    const float* x  = (const float*)d_in[0];
    const float* Wq = (const float*)d_in[1];
    const float* Wk = (const float*)d_in[2];
    const float* Wv = (const float*)d_in[3];
    const float* Wo = (const float*)d_in[4];
    float* out = (float*)d_out;

    float *pq, *pk, *pv, *pa;
    __nv_bfloat16 *xh, *xl, *ah, *al, *wh, *wl;
    cudaGetSymbolAddress((void**)&pq, g_q);
    cudaGetSymbolAddress((void**)&pk, g_k);
    cudaGetSymbolAddress((void**)&pv, g_v);
    cudaGetSymbolAddress((void**)&pa, g_att);
    cudaGetSymbolAddress((void**)&xh, g_xh);
    cudaGetSymbolAddress((void**)&xl, g_xl);
    cudaGetSymbolAddress((void**)&ah, g_ah);
    cudaGetSymbolAddress((void**)&al, g_al);
    cudaGetSymbolAddress((void**)&wh, g_wh);
    cudaGetSymbolAddress((void**)&wl, g_wl);

    cudaFuncSetAttribute(attn_kernel, cudaFuncAttributeMaxDynamicSharedMemorySize,
                         ATTN_SMEM);
    cudaFuncSetAttribute(gemm_bf16x2, cudaFuncAttributeMaxDynamicSharedMemorySize,
                         GSMEM);

    const size_t CC = (size_t)CD * CD;
    const int n4x = MD * CD / 4;
    const int n4w = (int)(CC / 4);

    split_kernel<<<n4x / 256, 256>>>(x, xh, xl, n4x);
    split_kernel<<<n4w / 256, 256>>>(Wq, wh + 0 * CC, wl + 0 * CC, n4w);
    split_kernel<<<n4w / 256, 256>>>(Wk, wh + 1 * CC, wl + 1 * CC, n4w);
    split_kernel<<<n4w / 256, 256>>>(Wv, wh + 2 * CC, wl + 2 * CC, n4w);
    split_kernel<<<n4w / 256, 256>>>(Wo, wh + 3 * CC, wl + 3 * CC, n4w);

    dim3 ggrid(CD / GBN, MD / GBM);   // (8, 64)
    gemm_bf16x2<<<ggrid, 256, GSMEM>>>(xh, xl, wh + 0 * CC, wl + 0 * CC, pq);
    gemm_bf16x2<<<ggrid, 256, GSMEM>>>(xh, xl, wh + 1 * CC, wl + 1 * CC, pk);
    gemm_bf16x2<<<ggrid, 256, GSMEM>>>(xh, xl, wh + 2 * CC, wl + 2 * CC, pv);

    attn_kernel<<<dim3(TD / 64, BD * NH), 256, ATTN_SMEM>>>(pq, pk, pv, pa);

    split_kernel<<<n4x / 256, 256>>>(pa, ah, al, n4x);
    gemm_bf16x2<<<ggrid, 256, GSMEM>>>(ah, al, wh + 3 * CC, wl + 3 * CC, out);
}

// round 9
// speedup vs baseline: 2.9523x; 1.5981x over previous
#include <cuda_runtime.h>
#include <cuda_bf16.h>
#include <cstdint>

#define CD 1024
#define BD 4
#define TD 2048
#define NH 16
#define HD 64
#define MD (BD*TD)   // 8192 rows

// Scratch (__device__ globals; allocation-free rule). All bf16 hi/lo pairs.
__device__ __nv_bfloat16 g_xh[(size_t)MD * CD];
__device__ __nv_bfloat16 g_xl[(size_t)MD * CD];
__device__ __nv_bfloat16 g_qh[(size_t)MD * CD];
__device__ __nv_bfloat16 g_ql[(size_t)MD * CD];
__device__ __nv_bfloat16 g_kh[(size_t)MD * CD];
__device__ __nv_bfloat16 g_kl[(size_t)MD * CD];
__device__ __nv_bfloat16 g_vh[(size_t)MD * CD];
__device__ __nv_bfloat16 g_vl[(size_t)MD * CD];
__device__ __nv_bfloat16 g_oh[(size_t)MD * CD];
__device__ __nv_bfloat16 g_ol[(size_t)MD * CD];
__device__ __nv_bfloat16 g_wh[4ull * CD * CD];
__device__ __nv_bfloat16 g_wl[4ull * CD * CD];

// ---------------------------------------------------------------------------
// helpers
// ---------------------------------------------------------------------------
__device__ __forceinline__ void cp_async16(uint32_t s, const void* g) {
    asm volatile("cp.async.cg.shared.global [%0], [%1], 16;\n" :: "r"(s), "l"(g));
}
__device__ __forceinline__ void cp_commit() {
    asm volatile("cp.async.commit_group;\n");
}
__device__ __forceinline__ void cp_wait0() {
    asm volatile("cp.async.wait_group 0;\n");
}
__device__ __forceinline__ void ldsm4(uint32_t* r, uint32_t a) {
    asm volatile("ldmatrix.sync.aligned.m8n8.x4.shared.b16 {%0,%1,%2,%3}, [%4];\n"
                 : "=r"(r[0]), "=r"(r[1]), "=r"(r[2]), "=r"(r[3]) : "r"(a));
}
__device__ __forceinline__ void ldsm4t(uint32_t* r, uint32_t a) {
    asm volatile("ldmatrix.sync.aligned.m8n8.x4.trans.shared.b16 {%0,%1,%2,%3}, [%4];\n"
                 : "=r"(r[0]), "=r"(r[1]), "=r"(r[2]), "=r"(r[3]) : "r"(a));
}
__device__ __forceinline__ void mma16816(float* c, const uint32_t* a,
                                         uint32_t b0, uint32_t b1) {
    asm volatile(
        "mma.sync.aligned.m16n8k16.row.col.f32.bf16.bf16.f32 "
        "{%0,%1,%2,%3},{%4,%5,%6,%7},{%8,%9},{%0,%1,%2,%3};\n"
        : "+f"(c[0]), "+f"(c[1]), "+f"(c[2]), "+f"(c[3])
        : "r"(a[0]), "r"(a[1]), "r"(a[2]), "r"(a[3]), "r"(b0), "r"(b1));
}
// pack two floats as bf16 hi pair + lo pair (low half = first arg)
__device__ __forceinline__ void pack_hilo(float a, float b, uint32_t& h, uint32_t& l) {
    __nv_bfloat16 ha = __float2bfloat16_rn(a), hb = __float2bfloat16_rn(b);
    __nv_bfloat162 H = __halves2bfloat162(ha, hb);
    __nv_bfloat162 L = __halves2bfloat162(
        __float2bfloat16_rn(a - __bfloat162float(ha)),
        __float2bfloat16_rn(b - __bfloat162float(hb)));
    h = *reinterpret_cast<uint32_t*>(&H);
    l = *reinterpret_cast<uint32_t*>(&L);
}

// ---------------------------------------------------------------------------
// fp32 -> (bf16 hi, bf16 lo) split (inputs x and the 4 weights only).
// ---------------------------------------------------------------------------
__global__ void split_kernel(const float* __restrict__ in,
                             __nv_bfloat16* __restrict__ hi,
                             __nv_bfloat16* __restrict__ lo, int n4) {
    int i = blockIdx.x * blockDim.x + threadIdx.x;
    if (i >= n4) return;
    float4 v = ((const float4*)in)[i];
    uint32_t h0, l0, h1, l1;
    pack_hilo(v.x, v.y, h0, l0);
    pack_hilo(v.z, v.w, h1, l1);
    ((uint32_t*)hi)[2 * i] = h0; ((uint32_t*)hi)[2 * i + 1] = h1;
    ((uint32_t*)lo)[2 * i] = l0; ((uint32_t*)lo)[2 * i + 1] = l1;
}

// ---------------------------------------------------------------------------
// Tensor-core GEMM: C[m,n] = sum_k A[m,k] * W[n,k] via 2-term bf16 split.
// CTA 128x128x32, 8 warps, cp.async double buffer. SPLIT: epilogue emits
// bf16 hi/lo instead of fp32.
// ---------------------------------------------------------------------------
#define GBM 128
#define GBN 128
#define GBK 32
#define TSTRIDE 40
#define TILE_H (128 * TSTRIDE)
#define STAGE_H (4 * TILE_H)
#define GSMEM (2 * STAGE_H * 2)

template <bool SPLIT>
__global__ void __launch_bounds__(256) gemm_bf16x2(
    const __nv_bfloat16* __restrict__ Ah, const __nv_bfloat16* __restrict__ Al,
    const __nv_bfloat16* __restrict__ Wh, const __nv_bfloat16* __restrict__ Wl,
    float* __restrict__ C,
    __nv_bfloat16* __restrict__ Ch, __nv_bfloat16* __restrict__ Cl) {
    extern __shared__ __align__(16) __nv_bfloat16 sm_g[];
    const uint32_t sbase = (uint32_t)__cvta_generic_to_shared(sm_g);
    const int tid = threadIdx.x;
    const int lane = tid & 31, warp = tid >> 5;
    const int wm = warp >> 1, wn = warp & 1;
    const int m0 = blockIdx.y * GBM;
    const int n0 = blockIdx.x * GBN;

    const int lrow = tid >> 2;
    const int lch = (tid & 3) * 8;
    const __nv_bfloat16* gp[4] = {
        Ah + (size_t)(m0 + lrow) * CD + lch,
        Al + (size_t)(m0 + lrow) * CD + lch,
        Wh + (size_t)(n0 + lrow) * CD + lch,
        Wl + (size_t)(n0 + lrow) * CD + lch};
    const uint32_t s_off = (uint32_t)(lrow * TSTRIDE + lch) * 2;

    const int lrow_a = (lane & 7) + ((lane >> 3) & 1) * 8;
    const int kca = (lane >> 4) * 8;
    const int lrow_b = (lane & 7) + (lane >> 4) * 8;
    const int kcb = ((lane >> 3) & 1) * 8;

    float acc[2][8][4];
    #pragma unroll
    for (int i = 0; i < 2; i++)
        #pragma unroll
        for (int j = 0; j < 8; j++)
            #pragma unroll
            for (int q = 0; q < 4; q++) acc[i][j][q] = 0.f;

    auto load_stage = [&](int s, int k0) {
        uint32_t so = sbase + (uint32_t)(s * STAGE_H) * 2;
        #pragma unroll
        for (int t = 0; t < 4; t++) {
            const __nv_bfloat16* g = gp[t] + k0;
            uint32_t sa = so + (uint32_t)(t * TILE_H) * 2 + s_off;
            cp_async16(sa, g);
            cp_async16(sa + 64 * TSTRIDE * 2, g + (size_t)64 * CD);
        }
    };

    load_stage(0, 0);
    cp_commit();

    const int NIT = CD / GBK;
    for (int it = 0; it < NIT; it++) {
        cp_wait0();
        __syncthreads();
        if (it + 1 < NIT) {
            load_stage((it + 1) & 1, (it + 1) * GBK);
            cp_commit();
        }
        uint32_t so = sbase + (uint32_t)((it & 1) * STAGE_H) * 2;
        #pragma unroll
        for (int ks = 0; ks < 2; ks++) {
            const int k0h = ks * 16;
            uint32_t ah[2][4], al[2][4];
            #pragma unroll
            for (int mt = 0; mt < 2; mt++) {
                int row = wm * 32 + mt * 16 + lrow_a;
                uint32_t a = so + (uint32_t)(row * TSTRIDE + k0h + kca) * 2;
                ldsm4(ah[mt], a);
                ldsm4(al[mt], a + TILE_H * 2);
            }
            uint32_t bh[4][4], bl[4][4];
            #pragma unroll
            for (int j = 0; j < 4; j++) {
                int nr = wn * 64 + j * 16 + lrow_b;
                uint32_t a = so + (uint32_t)(2 * TILE_H + nr * TSTRIDE + k0h + kcb) * 2;
                ldsm4(bh[j], a);
                ldsm4(bl[j], a + TILE_H * 2);
            }
            #pragma unroll
            for (int mt = 0; mt < 2; mt++)
                #pragma unroll
                for (int j = 0; j < 4; j++) {
                    mma16816(acc[mt][2 * j],     ah[mt], bh[j][0], bh[j][1]);
                    mma16816(acc[mt][2 * j],     ah[mt], bl[j][0], bl[j][1]);
                    mma16816(acc[mt][2 * j],     al[mt], bh[j][0], bh[j][1]);
                    mma16816(acc[mt][2 * j + 1], ah[mt], bh[j][2], bh[j][3]);
                    mma16816(acc[mt][2 * j + 1], ah[mt], bl[j][2], bl[j][3]);
                    mma16816(acc[mt][2 * j + 1], al[mt], bh[j][2], bh[j][3]);
                }
        }
    }

    const int cr = lane >> 2, cc = (lane & 3) * 2;
    #pragma unroll
    for (int mt = 0; mt < 2; mt++) {
        int r = m0 + wm * 32 + mt * 16 + cr;
        #pragma unroll
        for (int nt = 0; nt < 8; nt++) {
            int col = n0 + wn * 64 + nt * 8 + cc;
            if (SPLIT) {
                uint32_t h0, l0, h1, l1;
                pack_hilo(acc[mt][nt][0], acc[mt][nt][1], h0, l0);
                pack_hilo(acc[mt][nt][2], acc[mt][nt][3], h1, l1);
                *(uint32_t*)&Ch[(size_t)r * CD + col] = h0;
                *(uint32_t*)&Cl[(size_t)r * CD + col] = l0;
                *(uint32_t*)&Ch[(size_t)(r + 8) * CD + col] = h1;
                *(uint32_t*)&Cl[(size_t)(r + 8) * CD + col] = l1;
            } else {
                *(float2*)&C[(size_t)r * CD + col] =
                    make_float2(acc[mt][nt][0], acc[mt][nt][1]);
                *(float2*)&C[(size_t)(r + 8) * CD + col] =
                    make_float2(acc[mt][nt][2], acc[mt][nt][3]);
            }
        }
    }
}

// ---------------------------------------------------------------------------
// Flash attention (causal) on tensor cores, 2-term bf16 split throughout.
// CTA = 128 q-rows (8 warps x 16), KV tile 64. Double-buffered cp.async.
// ---------------------------------------------------------------------------
#define ATS 72                     // smem row stride (halves)
#define ATILE (64 * ATS)           // 4608 halves
#define ASTAGE (4 * ATILE)         // Kh,Kl,Vh,Vl
#define ATT_SMEM (2 * ASTAGE * 2)  // 73728 bytes

__global__ void __launch_bounds__(256, 1) attn_mma(
    const __nv_bfloat16* __restrict__ Qh, const __nv_bfloat16* __restrict__ Ql,
    const __nv_bfloat16* __restrict__ Kh, const __nv_bfloat16* __restrict__ Kl,
    const __nv_bfloat16* __restrict__ Vh, const __nv_bfloat16* __restrict__ Vl,
    __nv_bfloat16* __restrict__ Oh, __nv_bfloat16* __restrict__ Ol) {
    extern __shared__ __align__(16) __nv_bfloat16 sm_a[];
    const uint32_t sb = (uint32_t)__cvta_generic_to_shared(sm_a);
    const int tid = threadIdx.x;
    const int lane = tid & 31, warp = tid >> 5;
    const int qb = gridDim.x - 1 - blockIdx.x;     // heavy blocks first
    const int i0 = qb * 128;
    const int bh = blockIdx.y;
    const int b = bh >> 4, h = bh & 15;
    const size_t grow = (size_t)b * TD;            // row base
    const int gcol = h * HD;                       // col base

    // ldmatrix lane addressing
    const int lra = (lane & 7) + ((lane >> 3) & 1) * 8;  // A / V-trans row
    const int kca = (lane >> 4) * 8;                      // A / V-trans col
    const int lrb = (lane & 7) + (lane >> 4) * 8;         // B(K) row
    const int kcb = ((lane >> 3) & 1) * 8;                // B(K) col

    // ---- stage Q (128 x 64 hi+lo) into stage-0 buffer ----
    {
        #pragma unroll
        for (int k = 0; k < 4; k++) {
            int c = tid + k * 256;                 // 1024 chunks
            int row = c >> 3, colh = (c & 7) * 8;
            size_t g = (grow + i0 + row) * CD + gcol + colh;
            uint32_t sa = sb + (uint32_t)(row * ATS + colh) * 2;
            cp_async16(sa, Qh + g);
            cp_async16(sa + 2 * ATILE * 2, Ql + g);
        }
        cp_commit();
    }
    cp_wait0();
    __syncthreads();

    const int nit = qb * 2 + 2;

    auto load_kv = [&](int it) {
        uint32_t so = sb + (uint32_t)(((it + 1) & 1) * ASTAGE) * 2;
        int j0 = it * 64;
        #pragma unroll
        for (int k = 0; k < 2; k++) {
            int c = tid + k * 256;                 // 512 chunks per tile
            int row = c >> 3, colh = (c & 7) * 8;
            size_t g = (grow + j0 + row) * CD + gcol + colh;
            uint32_t sa = so + (uint32_t)(row * ATS + colh) * 2;
            cp_async16(sa, Kh + g);
            cp_async16(sa + ATILE * 2, Kl + g);
            cp_async16(sa + 2 * ATILE * 2, Vh + g);
            cp_async16(sa + 3 * ATILE * 2, Vl + g);
        }
        cp_commit();
    };

    load_kv(0);

    // ---- Q fragments from stage-0 ----
    uint32_t qfh[4][4], qfl[4][4];
    {
        int row = warp * 16 + lra;
        #pragma unroll
        for (int kt = 0; kt < 4; kt++) {
            uint32_t a = sb + (uint32_t)(row * ATS + kt * 16 + kca) * 2;
            ldsm4(qfh[kt], a);
            ldsm4(qfl[kt], a + 2 * ATILE * 2);
        }
    }
    __syncthreads();   // Q reads done before iter-1 overwrites stage 0

    float o[8][4];
    #pragma unroll
    for (int j = 0; j < 8; j++)
        #pragma unroll
        for (int q = 0; q < 4; q++) o[j][q] = 0.f;
    float m0r = -1e30f, m1r = -1e30f, l0r = 0.f, l1r = 0.f;

    const int wrow = i0 + warp * 16;               // warp's first q row

    for (int it = 0; it < nit; it++) {
        cp_wait0();
        __syncthreads();
        if (it + 1 < nit) load_kv(it + 1);
        uint32_t so = sb + (uint32_t)(((it + 1) & 1) * ASTAGE) * 2;
        const int j0 = it * 64;

        // ---- S = Q K^T ----
        float s[8][4];
        #pragma unroll
        for (int j = 0; j < 8; j++)
            #pragma unroll
            for (int q = 0; q < 4; q++) s[j][q] = 0.f;

        #pragma unroll
        for (int kt = 0; kt < 4; kt++) {
            #pragma unroll
            for (int jp = 0; jp < 4; jp++) {
                uint32_t a = so + (uint32_t)((jp * 16 + lrb) * ATS + kt * 16 + kcb) * 2;
                uint32_t bh4[4], bl4[4];
                ldsm4(bh4, a);
                ldsm4(bl4, a + ATILE * 2);
                mma16816(s[2 * jp],     qfh[kt], bh4[0], bh4[1]);
                mma16816(s[2 * jp],     qfl[kt], bh4[0], bh4[1]);
                mma16816(s[2 * jp],     qfh[kt], bl4[0], bl4[1]);
                mma16816(s[2 * jp + 1], qfh[kt], bh4[2], bh4[3]);
                mma16816(s[2 * jp + 1], qfl[kt], bh4[2], bh4[3]);
                mma16816(s[2 * jp + 1], qfh[kt], bl4[2], bl4[3]);
            }
        }

        // ---- scale + causal mask ----
        const int r0 = wrow + (lane >> 2);
        const int r1 = r0 + 8;
        const bool domask = (j0 + 63) > wrow;
        #pragma unroll
        for (int j = 0; j < 8; j++) {
            int c0 = j0 + j * 8 + (lane & 3) * 2;
            #pragma unroll
            for (int q = 0; q < 4; q++) {
                float sv = s[j][q] * 0.125f;
                if (domask) {
                    int col = c0 + (q & 1);
                    int row = (q < 2) ? r0 : r1;
                    if (col > row) sv = -1e30f;
                }
                s[j][q] = sv;
            }
        }

        // ---- online softmax ----
        float mx0 = -1e30f, mx1 = -1e30f;
        #pragma unroll
        for (int j = 0; j < 8; j++) {
            mx0 = fmaxf(mx0, fmaxf(s[j][0], s[j][1]));
            mx1 = fmaxf(mx1, fmaxf(s[j][2], s[j][3]));
        }
        mx0 = fmaxf(mx0, __shfl_xor_sync(0xffffffffu, mx0, 1));
        mx0 = fmaxf(mx0, __shfl_xor_sync(0xffffffffu, mx0, 2));
        mx1 = fmaxf(mx1, __shfl_xor_sync(0xffffffffu, mx1, 1));
        mx1 = fmaxf(mx1, __shfl_xor_sync(0xffffffffu, mx1, 2));
        float mn0 = fmaxf(m0r, mx0), mn1 = fmaxf(m1r, mx1);
        float corr0 = __expf(m0r - mn0), corr1 = __expf(m1r - mn1);
        float rs0 = 0.f, rs1 = 0.f;
        #pragma unroll
        for (int j = 0; j < 8; j++) {
            s[j][0] = __expf(s[j][0] - mn0);
            s[j][1] = __expf(s[j][1] - mn0);
            s[j][2] = __expf(s[j][2] - mn1);
            s[j][3] = __expf(s[j][3] - mn1);
            rs0 += s[j][0] + s[j][1];
            rs1 += s[j][2] + s[j][3];
        }
        rs0 += __shfl_xor_sync(0xffffffffu, rs0, 1);
        rs0 += __shfl_xor_sync(0xffffffffu, rs0, 2);
        rs1 += __shfl_xor_sync(0xffffffffu, rs1, 1);
        rs1 += __shfl_xor_sync(0xffffffffu, rs1, 2);
        l0r = l0r * corr0 + rs0;
        l1r = l1r * corr1 + rs1;
        m0r = mn0; m1r = mn1;
        #pragma unroll
        for (int j = 0; j < 8; j++) {
            o[j][0] *= corr0; o[j][1] *= corr0;
            o[j][2] *= corr1; o[j][3] *= corr1;
        }

        // ---- O += P V ----
        #pragma unroll
        for (int kt = 0; kt < 4; kt++) {
            uint32_t ph[4], pl[4];
            pack_hilo(s[2 * kt][0],     s[2 * kt][1],     ph[0], pl[0]);
            pack_hilo(s[2 * kt][2],     s[2 * kt][3],     ph[1], pl[1]);
            pack_hilo(s[2 * kt + 1][0], s[2 * kt + 1][1], ph[2], pl[2]);
            pack_hilo(s[2 * kt + 1][2], s[2 * kt + 1][3], ph[3], pl[3]);
            #pragma unroll
            for (int dn = 0; dn < 4; dn++) {
                uint32_t a = so + (uint32_t)(2 * ATILE + (kt * 16 + lra) * ATS +
                                             dn * 16 + kca) * 2;
                uint32_t vh4[4], vl4[4];
                ldsm4t(vh4, a);
                ldsm4t(vl4, a + ATILE * 2);
                mma16816(o[2 * dn],     ph, vh4[0], vh4[1]);
                mma16816(o[2 * dn],     pl, vh4[0], vh4[1]);
                mma16816(o[2 * dn],     ph, vl4[0], vl4[1]);
                mma16816(o[2 * dn + 1], ph, vh4[2], vh4[3]);
                mma16816(o[2 * dn + 1], pl, vh4[2], vh4[3]);
                mma16816(o[2 * dn + 1], ph, vl4[2], vl4[3]);
            }
        }
    }

    // ---- epilogue: normalize and write hi/lo O ----
    const float il0 = 1.0f / l0r, il1 = 1.0f / l1r;
    const int r0 = i0 + warp * 16 + (lane >> 2);
    #pragma unroll
    for (int j = 0; j < 8; j++) {
        int col = gcol + j * 8 + (lane & 3) * 2;
        uint32_t h0, l0, h1, l1;
        pack_hilo(o[j][0] * il0, o[j][1] * il0, h0, l0);
        pack_hilo(o[j][2] * il1, o[j][3] * il1, h1, l1);
        *(uint32_t*)&Oh[(grow + r0) * CD + col] = h0;
        *(uint32_t*)&Ol[(grow + r0) * CD + col] = l0;
        *(uint32_t*)&Oh[(grow + r0 + 8) * CD + col] = h1;
        *(uint32_t*)&Ol[(grow + r0 + 8) * CD + col] = l1;
    }
}

// ---------------------------------------------------------------------------

extern "C" void kernel_launch(void* const* d_in, const int* in_sizes, int n_in,
                              void* d_out, int out_size) {
    const float* x  = (const float*)d_in[0];
    const float* Wq = (const float*)d_in[1];
    const float* Wk = (const float*)d_in[2];
    const float* Wv = (const float*)d_in[3];
    const float* Wo = (const float*)d_in[4];
    float* out = (float*)d_out;

    __nv_bfloat16 *xh, *xl, *qh, *ql, *kh, *kl, *vh, *vl, *oh, *ol, *wh, *wl;
    cudaGetSymbolAddress((void**)&xh, g_xh);
    cudaGetSymbolAddress((void**)&xl, g_xl);
    cudaGetSymbolAddress((void**)&qh, g_qh);
    cudaGetSymbolAddress((void**)&ql, g_ql);
    cudaGetSymbolAddress((void**)&kh, g_kh);
    cudaGetSymbolAddress((void**)&kl, g_kl);
    cudaGetSymbolAddress((void**)&vh, g_vh);
    cudaGetSymbolAddress((void**)&vl, g_vl);
    cudaGetSymbolAddress((void**)&oh, g_oh);
    cudaGetSymbolAddress((void**)&ol, g_ol);
    cudaGetSymbolAddress((void**)&wh, g_wh);
    cudaGetSymbolAddress((void**)&wl, g_wl);

    cudaFuncSetAttribute(gemm_bf16x2<true>,
                         cudaFuncAttributeMaxDynamicSharedMemorySize, GSMEM);
    cudaFuncSetAttribute(gemm_bf16x2<false>,
                         cudaFuncAttributeMaxDynamicSharedMemorySize, GSMEM);
    cudaFuncSetAttribute(attn_mma,
                         cudaFuncAttributeMaxDynamicSharedMemorySize, ATT_SMEM);

    const size_t CC = (size_t)CD * CD;
    const int n4x = MD * CD / 4;
    const int n4w = (int)(CC / 4);

    split_kernel<<<n4x / 256, 256>>>(x, xh, xl, n4x);
    split_kernel<<<n4w / 256, 256>>>(Wq, wh + 0 * CC, wl + 0 * CC, n4w);
    split_kernel<<<n4w / 256, 256>>>(Wk, wh + 1 * CC, wl + 1 * CC, n4w);
    split_kernel<<<n4w / 256, 256>>>(Wv, wh + 2 * CC, wl + 2 * CC, n4w);
    split_kernel<<<n4w / 256, 256>>>(Wo, wh + 3 * CC, wl + 3 * CC, n4w);

    dim3 ggrid(CD / GBN, MD / GBM);   // (8, 64)
    gemm_bf16x2<true><<<ggrid, 256, GSMEM>>>(xh, xl, wh + 0 * CC, wl + 0 * CC,
                                             nullptr, qh, ql);
    gemm_bf16x2<true><<<ggrid, 256, GSMEM>>>(xh, xl, wh + 1 * CC, wl + 1 * CC,
                                             nullptr, kh, kl);
    gemm_bf16x2<true><<<ggrid, 256, GSMEM>>>(xh, xl, wh + 2 * CC, wl + 2 * CC,
                                             nullptr, vh, vl);

    attn_mma<<<dim3(TD / 128, BD * NH), 256, ATT_SMEM>>>(qh, ql, kh, kl, vh, vl,
                                                         oh, ol);

    gemm_bf16x2<false><<<ggrid, 256, GSMEM>>>(oh, ol, wh + 3 * CC, wl + 3 * CC,
                                              out, nullptr, nullptr);
}

// round 11
// speedup vs baseline: 4.5057x; 1.5262x over previous
#include <cuda_runtime.h>
#include <cuda_fp16.h>
#include <cstdint>

#define CD 1024
#define BD 4
#define TD 2048
#define NH 16
#define HD 64
#define MD (BD*TD)   // 8192 rows

// Scratch (__device__ globals; allocation-free rule). fp16.
__device__ __half g_xh[(size_t)MD * CD];
__device__ __half g_xl[(size_t)MD * CD];
__device__ __half g_qh[(size_t)MD * CD];
__device__ __half g_ql[(size_t)MD * CD];
__device__ __half g_kh[(size_t)MD * CD];
__device__ __half g_vh[(size_t)MD * CD];
__device__ __half g_oh[(size_t)MD * CD];
__device__ __half g_ol[(size_t)MD * CD];
__device__ __half g_wh[4ull * CD * CD];

// ---------------------------------------------------------------------------
// helpers
// ---------------------------------------------------------------------------
__device__ __forceinline__ void cp_async16(uint32_t s, const void* g) {
    asm volatile("cp.async.cg.shared.global [%0], [%1], 16;\n" :: "r"(s), "l"(g));
}
__device__ __forceinline__ void cp_commit() {
    asm volatile("cp.async.commit_group;\n");
}
__device__ __forceinline__ void cp_wait0() {
    asm volatile("cp.async.wait_group 0;\n");
}
__device__ __forceinline__ void ldsm4(uint32_t* r, uint32_t a) {
    asm volatile("ldmatrix.sync.aligned.m8n8.x4.shared.b16 {%0,%1,%2,%3}, [%4];\n"
                 : "=r"(r[0]), "=r"(r[1]), "=r"(r[2]), "=r"(r[3]) : "r"(a));
}
__device__ __forceinline__ void ldsm4t(uint32_t* r, uint32_t a) {
    asm volatile("ldmatrix.sync.aligned.m8n8.x4.trans.shared.b16 {%0,%1,%2,%3}, [%4];\n"
                 : "=r"(r[0]), "=r"(r[1]), "=r"(r[2]), "=r"(r[3]) : "r"(a));
}
__device__ __forceinline__ void mma16816(float* c, const uint32_t* a,
                                         uint32_t b0, uint32_t b1) {
    asm volatile(
        "mma.sync.aligned.m16n8k16.row.col.f32.f16.f16.f32 "
        "{%0,%1,%2,%3},{%4,%5,%6,%7},{%8,%9},{%0,%1,%2,%3};\n"
        : "+f"(c[0]), "+f"(c[1]), "+f"(c[2]), "+f"(c[3])
        : "r"(a[0]), "r"(a[1]), "r"(a[2]), "r"(a[3]), "r"(b0), "r"(b1));
}
// pack two floats as fp16 hi pair + lo pair (low half = first arg)
__device__ __forceinline__ void pack_hilo(float a, float b, uint32_t& h, uint32_t& l) {
    __half ha = __float2half_rn(a), hb = __float2half_rn(b);
    __half2 H = __halves2half2(ha, hb);
    __half2 L = __halves2half2(__float2half_rn(a - __half2float(ha)),
                               __float2half_rn(b - __half2float(hb)));
    h = *reinterpret_cast<uint32_t*>(&H);
    l = *reinterpret_cast<uint32_t*>(&L);
}

// ---------------------------------------------------------------------------
// fp32 -> (fp16 hi, fp16 lo) split (x only)  /  fp32 -> fp16 convert (weights)
// ---------------------------------------------------------------------------
__global__ void split_kernel(const float* __restrict__ in,
                             __half* __restrict__ hi,
                             __half* __restrict__ lo, int n4) {
    int i = blockIdx.x * blockDim.x + threadIdx.x;
    if (i >= n4) return;
    float4 v = ((const float4*)in)[i];
    uint32_t h0, l0, h1, l1;
    pack_hilo(v.x, v.y, h0, l0);
    pack_hilo(v.z, v.w, h1, l1);
    ((uint32_t*)hi)[2 * i] = h0; ((uint32_t*)hi)[2 * i + 1] = h1;
    ((uint32_t*)lo)[2 * i] = l0; ((uint32_t*)lo)[2 * i + 1] = l1;
}
__global__ void conv_kernel(const float* __restrict__ in,
                            __half* __restrict__ out, int n4) {
    int i = blockIdx.x * blockDim.x + threadIdx.x;
    if (i >= n4) return;
    float4 v = ((const float4*)in)[i];
    __half2 a = __floats2half2_rn(v.x, v.y);
    __half2 b = __floats2half2_rn(v.z, v.w);
    ((uint32_t*)out)[2 * i]     = *reinterpret_cast<uint32_t*>(&a);
    ((uint32_t*)out)[2 * i + 1] = *reinterpret_cast<uint32_t*>(&b);
}

// ---------------------------------------------------------------------------
// Tensor-core GEMM: C[m,n] = sum_k A[m,k] * W[n,k].
// A = 2-term fp16 split (exact to 2^-22), W = single fp16 -> 2 MMAs/step.
// CTA 128x128x32, 8 warps (warp tile 32x64), cp.async double buffer.
// OM: 0 = fp32 out, 1 = split fp16 pair out, 2 = single fp16 out.
// ---------------------------------------------------------------------------
#define TSTRIDE 40
#define TILE_H (128 * TSTRIDE)
#define STAGE_H (3 * TILE_H)          // Ah, Al, Wh
#define GSMEM (2 * STAGE_H * 2)       // 61440 bytes

template <int OM>
__global__ void __launch_bounds__(256, 2) gemm_f16(
    const __half* __restrict__ Ah, const __half* __restrict__ Al,
    const __half* __restrict__ Wh,
    float* __restrict__ C, __half* __restrict__ Ch, __half* __restrict__ Cl) {
    extern __shared__ __align__(16) __half sm_g[];
    const uint32_t sbase = (uint32_t)__cvta_generic_to_shared(sm_g);
    const int tid = threadIdx.x;
    const int lane = tid & 31, warp = tid >> 5;
    const int wm = warp >> 1, wn = warp & 1;
    const int m0 = blockIdx.y * 128;
    const int n0 = blockIdx.x * 128;

    const int lrow = tid >> 2;
    const int lch = (tid & 3) * 8;
    const __half* gp[3] = {
        Ah + (size_t)(m0 + lrow) * CD + lch,
        Al + (size_t)(m0 + lrow) * CD + lch,
        Wh + (size_t)(n0 + lrow) * CD + lch};
    const uint32_t s_off = (uint32_t)(lrow * TSTRIDE + lch) * 2;

    const int lrow_a = (lane & 7) + ((lane >> 3) & 1) * 8;
    const int kca = (lane >> 4) * 8;
    const int lrow_b = (lane & 7) + (lane >> 4) * 8;
    const int kcb = ((lane >> 3) & 1) * 8;

    float acc[2][8][4];
    #pragma unroll
    for (int i = 0; i < 2; i++)
        #pragma unroll
        for (int j = 0; j < 8; j++)
            #pragma unroll
            for (int q = 0; q < 4; q++) acc[i][j][q] = 0.f;

    auto load_stage = [&](int s, int k0) {
        uint32_t so = sbase + (uint32_t)(s * STAGE_H) * 2;
        #pragma unroll
        for (int t = 0; t < 3; t++) {
            const __half* g = gp[t] + k0;
            uint32_t sa = so + (uint32_t)(t * TILE_H) * 2 + s_off;
            cp_async16(sa, g);
            cp_async16(sa + 64 * TSTRIDE * 2, g + (size_t)64 * CD);
        }
    };

    load_stage(0, 0);
    cp_commit();

    const int NIT = CD / 32;
    for (int it = 0; it < NIT; it++) {
        cp_wait0();
        __syncthreads();
        if (it + 1 < NIT) {
            load_stage((it + 1) & 1, (it + 1) * 32);
            cp_commit();
        }
        uint32_t so = sbase + (uint32_t)((it & 1) * STAGE_H) * 2;
        #pragma unroll
        for (int ks = 0; ks < 2; ks++) {
            const int k0h = ks * 16;
            uint32_t ah[2][4], al[2][4];
            #pragma unroll
            for (int mt = 0; mt < 2; mt++) {
                int row = wm * 32 + mt * 16 + lrow_a;
                uint32_t a = so + (uint32_t)(row * TSTRIDE + k0h + kca) * 2;
                ldsm4(ah[mt], a);
                ldsm4(al[mt], a + TILE_H * 2);
            }
            uint32_t bw[4][4];
            #pragma unroll
            for (int j = 0; j < 4; j++) {
                int nr = wn * 64 + j * 16 + lrow_b;
                uint32_t a = so + (uint32_t)(2 * TILE_H + nr * TSTRIDE + k0h + kcb) * 2;
                ldsm4(bw[j], a);
            }
            #pragma unroll
            for (int mt = 0; mt < 2; mt++)
                #pragma unroll
                for (int j = 0; j < 4; j++) {
                    mma16816(acc[mt][2 * j],     ah[mt], bw[j][0], bw[j][1]);
                    mma16816(acc[mt][2 * j + 1], ah[mt], bw[j][2], bw[j][3]);
                    mma16816(acc[mt][2 * j],     al[mt], bw[j][0], bw[j][1]);
                    mma16816(acc[mt][2 * j + 1], al[mt], bw[j][2], bw[j][3]);
                }
        }
    }

    const int cr = lane >> 2, cc = (lane & 3) * 2;
    #pragma unroll
    for (int mt = 0; mt < 2; mt++) {
        int r = m0 + wm * 32 + mt * 16 + cr;
        #pragma unroll
        for (int nt = 0; nt < 8; nt++) {
            int col = n0 + wn * 64 + nt * 8 + cc;
            if (OM == 1) {
                uint32_t h0, l0, h1, l1;
                pack_hilo(acc[mt][nt][0], acc[mt][nt][1], h0, l0);
                pack_hilo(acc[mt][nt][2], acc[mt][nt][3], h1, l1);
                *(uint32_t*)&Ch[(size_t)r * CD + col] = h0;
                *(uint32_t*)&Cl[(size_t)r * CD + col] = l0;
                *(uint32_t*)&Ch[(size_t)(r + 8) * CD + col] = h1;
                *(uint32_t*)&Cl[(size_t)(r + 8) * CD + col] = l1;
            } else if (OM == 2) {
                __half2 v0 = __floats2half2_rn(acc[mt][nt][0], acc[mt][nt][1]);
                __half2 v1 = __floats2half2_rn(acc[mt][nt][2], acc[mt][nt][3]);
                *(uint32_t*)&Ch[(size_t)r * CD + col] = *(uint32_t*)&v0;
                *(uint32_t*)&Ch[(size_t)(r + 8) * CD + col] = *(uint32_t*)&v1;
            } else {
                *(float2*)&C[(size_t)r * CD + col] =
                    make_float2(acc[mt][nt][0], acc[mt][nt][1]);
                *(float2*)&C[(size_t)(r + 8) * CD + col] =
                    make_float2(acc[mt][nt][2], acc[mt][nt][3]);
            }
        }
    }
}

// ---------------------------------------------------------------------------
// Flash attention (causal), fp16 tensor cores.
// Q split (Qh+Ql), K single, V single, P split in-register.
// CTA = 128 q-rows (8 warps x 16), KV tile 64, double-buffered cp.async.
// Stage = [Kh | Vh] (2 tiles). During prologue Q occupies both stages
// (Qh = tiles 0-1, Ql = tiles 2-3); Q frags are read BEFORE load_kv(0).
// ---------------------------------------------------------------------------
#define ATS 72                     // smem row stride (halves)
#define ATILE (64 * ATS)           // halves per 64-row tile
#define ASTAGE (2 * ATILE)         // Kh, Vh
#define ATT_SMEM (2 * ASTAGE * 2)  // 36864 bytes

__global__ void __launch_bounds__(256, 1) attn_mma(
    const __half* __restrict__ Qh, const __half* __restrict__ Ql,
    const __half* __restrict__ Kh, const __half* __restrict__ Vh,
    __half* __restrict__ Oh, __half* __restrict__ Ol) {
    extern __shared__ __align__(16) __half sm_a[];
    const uint32_t sb = (uint32_t)__cvta_generic_to_shared(sm_a);
    const int tid = threadIdx.x;
    const int lane = tid & 31, warp = tid >> 5;
    const int qb = gridDim.x - 1 - blockIdx.x;     // heavy blocks first
    const int i0 = qb * 128;
    const int bh = blockIdx.y;
    const int b = bh >> 4, h = bh & 15;
    const size_t grow = (size_t)b * TD;
    const int gcol = h * HD;

    const int lra = (lane & 7) + ((lane >> 3) & 1) * 8;
    const int kca = (lane >> 4) * 8;
    const int lrb = (lane & 7) + (lane >> 4) * 8;
    const int kcb = ((lane >> 3) & 1) * 8;

    // ---- stage Q (128 x 64 hi+lo) across the whole smem buffer ----
    {
        #pragma unroll
        for (int k = 0; k < 4; k++) {
            int c = tid + k * 256;                 // 1024 chunks
            int row = c >> 3, colh = (c & 7) * 8;
            size_t g = (grow + i0 + row) * CD + gcol + colh;
            uint32_t sa = sb + (uint32_t)(row * ATS + colh) * 2;
            cp_async16(sa, Qh + g);
            cp_async16(sa + 2 * ATILE * 2, Ql + g);
        }
        cp_commit();
    }
    cp_wait0();
    __syncthreads();

    // ---- Q fragments (must complete before any KV load overwrites smem) ----
    uint32_t qfh[4][4], qfl[4][4];
    {
        int row = warp * 16 + lra;
        #pragma unroll
        for (int kt = 0; kt < 4; kt++) {
            uint32_t a = sb + (uint32_t)(row * ATS + kt * 16 + kca) * 2;
            ldsm4(qfh[kt], a);
            ldsm4(qfl[kt], a + 2 * ATILE * 2);
        }
    }
    __syncthreads();   // all warps done reading Q

    const int nit = qb * 2 + 2;

    auto load_kv = [&](int it) {
        uint32_t so = sb + (uint32_t)(((it + 1) & 1) * ASTAGE) * 2;
        int j0 = it * 64;
        #pragma unroll
        for (int k = 0; k < 2; k++) {
            int c = tid + k * 256;                 // 512 chunks per tile
            int row = c >> 3, colh = (c & 7) * 8;
            size_t g = (grow + j0 + row) * CD + gcol + colh;
            uint32_t sa = so + (uint32_t)(row * ATS + colh) * 2;
            cp_async16(sa, Kh + g);
            cp_async16(sa + ATILE * 2, Vh + g);
        }
        cp_commit();
    };

    load_kv(0);

    float o[8][4];
    #pragma unroll
    for (int j = 0; j < 8; j++)
        #pragma unroll
        for (int q = 0; q < 4; q++) o[j][q] = 0.f;
    float m0r = -1e30f, m1r = -1e30f, l0r = 0.f, l1r = 0.f;

    const int wrow = i0 + warp * 16;

    for (int it = 0; it < nit; it++) {
        cp_wait0();
        __syncthreads();
        if (it + 1 < nit) load_kv(it + 1);
        uint32_t so = sb + (uint32_t)(((it + 1) & 1) * ASTAGE) * 2;
        const int j0 = it * 64;

        // ---- S = Q K^T ----
        float s[8][4];
        #pragma unroll
        for (int j = 0; j < 8; j++)
            #pragma unroll
            for (int q = 0; q < 4; q++) s[j][q] = 0.f;

        #pragma unroll
        for (int kt = 0; kt < 4; kt++) {
            #pragma unroll
            for (int jp = 0; jp < 4; jp++) {
                uint32_t a = so + (uint32_t)((jp * 16 + lrb) * ATS + kt * 16 + kcb) * 2;
                uint32_t b4[4];
                ldsm4(b4, a);
                mma16816(s[2 * jp],     qfh[kt], b4[0], b4[1]);
                mma16816(s[2 * jp + 1], qfh[kt], b4[2], b4[3]);
                mma16816(s[2 * jp],     qfl[kt], b4[0], b4[1]);
                mma16816(s[2 * jp + 1], qfl[kt], b4[2], b4[3]);
            }
        }

        // ---- scale + causal mask ----
        const int r0 = wrow + (lane >> 2);
        const int r1 = r0 + 8;
        const bool domask = (j0 + 63) > wrow;
        #pragma unroll
        for (int j = 0; j < 8; j++) {
            int c0 = j0 + j * 8 + (lane & 3) * 2;
            #pragma unroll
            for (int q = 0; q < 4; q++) {
                float sv = s[j][q] * 0.125f;
                if (domask) {
                    int col = c0 + (q & 1);
                    int row = (q < 2) ? r0 : r1;
                    if (col > row) sv = -1e30f;
                }
                s[j][q] = sv;
            }
        }

        // ---- online softmax ----
        float mx0 = -1e30f, mx1 = -1e30f;
        #pragma unroll
        for (int j = 0; j < 8; j++) {
            mx0 = fmaxf(mx0, fmaxf(s[j][0], s[j][1]));
            mx1 = fmaxf(mx1, fmaxf(s[j][2], s[j][3]));
        }
        mx0 = fmaxf(mx0, __shfl_xor_sync(0xffffffffu, mx0, 1));
        mx0 = fmaxf(mx0, __shfl_xor_sync(0xffffffffu, mx0, 2));
        mx1 = fmaxf(mx1, __shfl_xor_sync(0xffffffffu, mx1, 1));
        mx1 = fmaxf(mx1, __shfl_xor_sync(0xffffffffu, mx1, 2));
        float mn0 = fmaxf(m0r, mx0), mn1 = fmaxf(m1r, mx1);
        float corr0 = __expf(m0r - mn0), corr1 = __expf(m1r - mn1);
        float rs0 = 0.f, rs1 = 0.f;
        #pragma unroll
        for (int j = 0; j < 8; j++) {
            s[j][0] = __expf(s[j][0] - mn0);
            s[j][1] = __expf(s[j][1] - mn0);
            s[j][2] = __expf(s[j][2] - mn1);
            s[j][3] = __expf(s[j][3] - mn1);
            rs0 += s[j][0] + s[j][1];
            rs1 += s[j][2] + s[j][3];
        }
        rs0 += __shfl_xor_sync(0xffffffffu, rs0, 1);
        rs0 += __shfl_xor_sync(0xffffffffu, rs0, 2);
        rs1 += __shfl_xor_sync(0xffffffffu, rs1, 1);
        rs1 += __shfl_xor_sync(0xffffffffu, rs1, 2);
        l0r = l0r * corr0 + rs0;
        l1r = l1r * corr1 + rs1;
        m0r = mn0; m1r = mn1;
        #pragma unroll
        for (int j = 0; j < 8; j++) {
            o[j][0] *= corr0; o[j][1] *= corr0;
            o[j][2] *= corr1; o[j][3] *= corr1;
        }

        // ---- O += P V (P split, V single) ----
        #pragma unroll
        for (int kt = 0; kt < 4; kt++) {
            uint32_t ph[4], pl[4];
            pack_hilo(s[2 * kt][0],     s[2 * kt][1],     ph[0], pl[0]);
            pack_hilo(s[2 * kt][2],     s[2 * kt][3],     ph[1], pl[1]);
            pack_hilo(s[2 * kt + 1][0], s[2 * kt + 1][1], ph[2], pl[2]);
            pack_hilo(s[2 * kt + 1][2], s[2 * kt + 1][3], ph[3], pl[3]);
            #pragma unroll
            for (int dn = 0; dn < 4; dn++) {
                uint32_t a = so + (uint32_t)(ATILE + (kt * 16 + lra) * ATS +
                                             dn * 16 + kca) * 2;
                uint32_t v4[4];
                ldsm4t(v4, a);
                mma16816(o[2 * dn],     ph, v4[0], v4[1]);
                mma16816(o[2 * dn + 1], ph, v4[2], v4[3]);
                mma16816(o[2 * dn],     pl, v4[0], v4[1]);
                mma16816(o[2 * dn + 1], pl, v4[2], v4[3]);
            }
        }
    }

    // ---- epilogue: normalize and write hi/lo O ----
    const float il0 = 1.0f / l0r, il1 = 1.0f / l1r;
    const int r0 = i0 + warp * 16 + (lane >> 2);
    #pragma unroll
    for (int j = 0; j < 8; j++) {
        int col = gcol + j * 8 + (lane & 3) * 2;
        uint32_t h0, l0, h1, l1;
        pack_hilo(o[j][0] * il0, o[j][1] * il0, h0, l0);
        pack_hilo(o[j][2] * il1, o[j][3] * il1, h1, l1);
        *(uint32_t*)&Oh[(grow + r0) * CD + col] = h0;
        *(uint32_t*)&Ol[(grow + r0) * CD + col] = l0;
        *(uint32_t*)&Oh[(grow + r0 + 8) * CD + col] = h1;
        *(uint32_t*)&Ol[(grow + r0 + 8) * CD + col] = l1;
    }
}

// ---------------------------------------------------------------------------

extern "C" void kernel_launch(void* const* d_in, const int* in_sizes, int n_in,
                              void* d_out, int out_size) {
    const float* x  = (const float*)d_in[0];
    const float* Wq = (const float*)d_in[1];
    const float* Wk = (const float*)d_in[2];
    const float* Wv = (const float*)d_in[3];
    const float* Wo = (const float*)d_in[4];
    float* out = (float*)d_out;

    __half *xh, *xl, *qh, *ql, *kh, *vh, *oh, *ol, *wh;
    cudaGetSymbolAddress((void**)&xh, g_xh);
    cudaGetSymbolAddress((void**)&xl, g_xl);
    cudaGetSymbolAddress((void**)&qh, g_qh);
    cudaGetSymbolAddress((void**)&ql, g_ql);
    cudaGetSymbolAddress((void**)&kh, g_kh);
    cudaGetSymbolAddress((void**)&vh, g_vh);
    cudaGetSymbolAddress((void**)&oh, g_oh);
    cudaGetSymbolAddress((void**)&ol, g_ol);
    cudaGetSymbolAddress((void**)&wh, g_wh);

    cudaFuncSetAttribute(gemm_f16<0>,
                         cudaFuncAttributeMaxDynamicSharedMemorySize, GSMEM);
    cudaFuncSetAttribute(gemm_f16<1>,
                         cudaFuncAttributeMaxDynamicSharedMemorySize, GSMEM);
    cudaFuncSetAttribute(gemm_f16<2>,
                         cudaFuncAttributeMaxDynamicSharedMemorySize, GSMEM);
    cudaFuncSetAttribute(attn_mma,
                         cudaFuncAttributeMaxDynamicSharedMemorySize, ATT_SMEM);

    const size_t CC = (size_t)CD * CD;
    const int n4x = MD * CD / 4;
    const int n4w = (int)(CC / 4);

    split_kernel<<<n4x / 256, 256>>>(x, xh, xl, n4x);
    conv_kernel<<<n4w / 256, 256>>>(Wq, wh + 0 * CC, n4w);
    conv_kernel<<<n4w / 256, 256>>>(Wk, wh + 1 * CC, n4w);
    conv_kernel<<<n4w / 256, 256>>>(Wv, wh + 2 * CC, n4w);
    conv_kernel<<<n4w / 256, 256>>>(Wo, wh + 3 * CC, n4w);

    dim3 ggrid(CD / 128, MD / 128);   // (8, 64)
    gemm_f16<1><<<ggrid, 256, GSMEM>>>(xh, xl, wh + 0 * CC, nullptr, qh, ql);
    gemm_f16<2><<<ggrid, 256, GSMEM>>>(xh, xl, wh + 1 * CC, nullptr, kh, nullptr);
    gemm_f16<2><<<ggrid, 256, GSMEM>>>(xh, xl, wh + 2 * CC, nullptr, vh, nullptr);

    attn_mma<<<dim3(TD / 128, BD * NH), 256, ATT_SMEM>>>(qh, ql, kh, vh, oh, ol);

    gemm_f16<0><<<ggrid, 256, GSMEM>>>(oh, ol, wh + 3 * CC, out, nullptr, nullptr);
}

// round 12
// speedup vs baseline: 5.8980x; 1.3090x over previous
#include <cuda_runtime.h>
#include <cuda_fp16.h>
#include <cstdint>

#define CD 1024
#define BD 4
#define TD 2048
#define NH 16
#define HD 64
#define MD (BD*TD)   // 8192 rows

// Scratch (__device__ globals; allocation-free rule). fp16.
__device__ __half g_xh[(size_t)MD * CD];
__device__ __half g_qh[(size_t)MD * CD];
__device__ __half g_ql[(size_t)MD * CD];
__device__ __half g_kh[(size_t)MD * CD];
__device__ __half g_vh[(size_t)MD * CD];
__device__ __half g_oh[(size_t)MD * CD];
__device__ __half g_ol[(size_t)MD * CD];
__device__ __half g_wh[4ull * CD * CD];

// ---------------------------------------------------------------------------
// helpers
// ---------------------------------------------------------------------------
__device__ __forceinline__ void cp_async16(uint32_t s, const void* g) {
    asm volatile("cp.async.cg.shared.global [%0], [%1], 16;\n" :: "r"(s), "l"(g));
}
__device__ __forceinline__ void cp_commit() {
    asm volatile("cp.async.commit_group;\n");
}
__device__ __forceinline__ void cp_wait0() {
    asm volatile("cp.async.wait_group 0;\n");
}
__device__ __forceinline__ void ldsm4(uint32_t* r, uint32_t a) {
    asm volatile("ldmatrix.sync.aligned.m8n8.x4.shared.b16 {%0,%1,%2,%3}, [%4];\n"
                 : "=r"(r[0]), "=r"(r[1]), "=r"(r[2]), "=r"(r[3]) : "r"(a));
}
__device__ __forceinline__ void ldsm4t(uint32_t* r, uint32_t a) {
    asm volatile("ldmatrix.sync.aligned.m8n8.x4.trans.shared.b16 {%0,%1,%2,%3}, [%4];\n"
                 : "=r"(r[0]), "=r"(r[1]), "=r"(r[2]), "=r"(r[3]) : "r"(a));
}
__device__ __forceinline__ void mma16816(float* c, const uint32_t* a,
                                         uint32_t b0, uint32_t b1) {
    asm volatile(
        "mma.sync.aligned.m16n8k16.row.col.f32.f16.f16.f32 "
        "{%0,%1,%2,%3},{%4,%5,%6,%7},{%8,%9},{%0,%1,%2,%3};\n"
        : "+f"(c[0]), "+f"(c[1]), "+f"(c[2]), "+f"(c[3])
        : "r"(a[0]), "r"(a[1]), "r"(a[2]), "r"(a[3]), "r"(b0), "r"(b1));
}
// pack two floats as fp16 hi pair + lo pair (low half = first arg)
__device__ __forceinline__ void pack_hilo(float a, float b, uint32_t& h, uint32_t& l) {
    __half ha = __float2half_rn(a), hb = __float2half_rn(b);
    __half2 H = __halves2half2(ha, hb);
    __half2 L = __halves2half2(__float2half_rn(a - __half2float(ha)),
                               __float2half_rn(b - __half2float(hb)));
    h = *reinterpret_cast<uint32_t*>(&H);
    l = *reinterpret_cast<uint32_t*>(&L);
}

// ---------------------------------------------------------------------------
// fp32 -> fp16 converts: x (single tensor) and all four weights (fused).
// ---------------------------------------------------------------------------
__global__ void conv_kernel(const float* __restrict__ in,
                            __half* __restrict__ out, int n4) {
    int i = blockIdx.x * blockDim.x + threadIdx.x;
    if (i >= n4) return;
    float4 v = ((const float4*)in)[i];
    __half2 a = __floats2half2_rn(v.x, v.y);
    __half2 b = __floats2half2_rn(v.z, v.w);
    ((uint32_t*)out)[2 * i]     = *reinterpret_cast<uint32_t*>(&a);
    ((uint32_t*)out)[2 * i + 1] = *reinterpret_cast<uint32_t*>(&b);
}
// 4 weights, 1024 blocks each (CC/4 = 262144 chunks = 1024 * 256)
__global__ void conv4_kernel(const float* __restrict__ w0,
                             const float* __restrict__ w1,
                             const float* __restrict__ w2,
                             const float* __restrict__ w3,
                             __half* __restrict__ out) {
    const int which = blockIdx.x >> 10;
    const int j = (blockIdx.x & 1023) * 256 + threadIdx.x;
    const float* in = (which == 0) ? w0 : (which == 1) ? w1 :
                      (which == 2) ? w2 : w3;
    float4 v = ((const float4*)in)[j];
    __half2 a = __floats2half2_rn(v.x, v.y);
    __half2 b = __floats2half2_rn(v.z, v.w);
    __half* o = out + (size_t)which * CD * CD;
    ((uint32_t*)o)[2 * j]     = *reinterpret_cast<uint32_t*>(&a);
    ((uint32_t*)o)[2 * j + 1] = *reinterpret_cast<uint32_t*>(&b);
}

// ---------------------------------------------------------------------------
// Fused QKV GEMM, plain fp16 (1 MMA/step): for which = blockIdx.x>>3:
//   0: Q = x@Wq^T  -> split fp16 pair (qh, ql)
//   1: K = x@Wk^T  -> single fp16
//   2: V = x@Wv^T  -> single fp16
// CTA 128x128x32, 8 warps (warp tile 32x64), cp.async double buffer.
// ---------------------------------------------------------------------------
#define TSTRIDE 40
#define TILE_H (128 * TSTRIDE)
#define STAGE2_H (2 * TILE_H)          // X, W
#define QSMEM (2 * STAGE2_H * 2)       // 40960 bytes

__global__ void __launch_bounds__(256, 2) gemm_qkv(
    const __half* __restrict__ X, const __half* __restrict__ Wall,
    __half* __restrict__ Qh, __half* __restrict__ Ql,
    __half* __restrict__ Kh, __half* __restrict__ Vh) {
    extern __shared__ __align__(16) __half sm_g[];
    const uint32_t sbase = (uint32_t)__cvta_generic_to_shared(sm_g);
    const int tid = threadIdx.x;
    const int lane = tid & 31, warp = tid >> 5;
    const int wm = warp >> 1, wn = warp & 1;
    const int which = blockIdx.x >> 3;
    const int n0 = (blockIdx.x & 7) * 128;
    const int m0 = blockIdx.y * 128;

    const int lrow = tid >> 2;
    const int lch = (tid & 3) * 8;
    const __half* gp[2] = {
        X + (size_t)(m0 + lrow) * CD + lch,
        Wall + (size_t)which * CD * CD + (size_t)(n0 + lrow) * CD + lch};
    const uint32_t s_off = (uint32_t)(lrow * TSTRIDE + lch) * 2;

    const int lrow_a = (lane & 7) + ((lane >> 3) & 1) * 8;
    const int kca = (lane >> 4) * 8;
    const int lrow_b = (lane & 7) + (lane >> 4) * 8;
    const int kcb = ((lane >> 3) & 1) * 8;

    float acc[2][8][4];
    #pragma unroll
    for (int i = 0; i < 2; i++)
        #pragma unroll
        for (int j = 0; j < 8; j++)
            #pragma unroll
            for (int q = 0; q < 4; q++) acc[i][j][q] = 0.f;

    auto load_stage = [&](int s, int k0) {
        uint32_t so = sbase + (uint32_t)(s * STAGE2_H) * 2;
        #pragma unroll
        for (int t = 0; t < 2; t++) {
            const __half* g = gp[t] + k0;
            uint32_t sa = so + (uint32_t)(t * TILE_H) * 2 + s_off;
            cp_async16(sa, g);
            cp_async16(sa + 64 * TSTRIDE * 2, g + (size_t)64 * CD);
        }
    };

    load_stage(0, 0);
    cp_commit();

    const int NIT = CD / 32;
    for (int it = 0; it < NIT; it++) {
        cp_wait0();
        __syncthreads();
        if (it + 1 < NIT) {
            load_stage((it + 1) & 1, (it + 1) * 32);
            cp_commit();
        }
        uint32_t so = sbase + (uint32_t)((it & 1) * STAGE2_H) * 2;
        #pragma unroll
        for (int ks = 0; ks < 2; ks++) {
            const int k0h = ks * 16;
            uint32_t ah[2][4];
            #pragma unroll
            for (int mt = 0; mt < 2; mt++) {
                int row = wm * 32 + mt * 16 + lrow_a;
                ldsm4(ah[mt], so + (uint32_t)(row * TSTRIDE + k0h + kca) * 2);
            }
            uint32_t bw[4][4];
            #pragma unroll
            for (int j = 0; j < 4; j++) {
                int nr = wn * 64 + j * 16 + lrow_b;
                ldsm4(bw[j], so + (uint32_t)(TILE_H + nr * TSTRIDE + k0h + kcb) * 2);
            }
            #pragma unroll
            for (int mt = 0; mt < 2; mt++)
                #pragma unroll
                for (int j = 0; j < 4; j++) {
                    mma16816(acc[mt][2 * j],     ah[mt], bw[j][0], bw[j][1]);
                    mma16816(acc[mt][2 * j + 1], ah[mt], bw[j][2], bw[j][3]);
                }
        }
    }

    const int cr = lane >> 2, cc = (lane & 3) * 2;
    #pragma unroll
    for (int mt = 0; mt < 2; mt++) {
        int r = m0 + wm * 32 + mt * 16 + cr;
        #pragma unroll
        for (int nt = 0; nt < 8; nt++) {
            int col = n0 + wn * 64 + nt * 8 + cc;
            if (which == 0) {
                uint32_t h0, l0, h1, l1;
                pack_hilo(acc[mt][nt][0], acc[mt][nt][1], h0, l0);
                pack_hilo(acc[mt][nt][2], acc[mt][nt][3], h1, l1);
                *(uint32_t*)&Qh[(size_t)r * CD + col] = h0;
                *(uint32_t*)&Ql[(size_t)r * CD + col] = l0;
                *(uint32_t*)&Qh[(size_t)(r + 8) * CD + col] = h1;
                *(uint32_t*)&Ql[(size_t)(r + 8) * CD + col] = l1;
            } else {
                __half* D = (which == 1) ? Kh : Vh;
                __half2 v0 = __floats2half2_rn(acc[mt][nt][0], acc[mt][nt][1]);
                __half2 v1 = __floats2half2_rn(acc[mt][nt][2], acc[mt][nt][3]);
                *(uint32_t*)&D[(size_t)r * CD + col] = *(uint32_t*)&v0;
                *(uint32_t*)&D[(size_t)(r + 8) * CD + col] = *(uint32_t*)&v1;
            }
        }
    }
}

// ---------------------------------------------------------------------------
// Output GEMM: out = O@Wo^T, O = 2-term fp16 split (2 MMAs/step), fp32 out.
// CTA 128x128x32, 3-tile stages (Oh, Ol, Wo), cp.async double buffer.
// ---------------------------------------------------------------------------
#define STAGE3_H (3 * TILE_H)
#define WSMEM (2 * STAGE3_H * 2)       // 61440 bytes

__global__ void __launch_bounds__(256, 2) gemm_wo(
    const __half* __restrict__ Ah, const __half* __restrict__ Al,
    const __half* __restrict__ Wh, float* __restrict__ C) {
    extern __shared__ __align__(16) __half sm_g[];
    const uint32_t sbase = (uint32_t)__cvta_generic_to_shared(sm_g);
    const int tid = threadIdx.x;
    const int lane = tid & 31, warp = tid >> 5;
    const int wm = warp >> 1, wn = warp & 1;
    const int m0 = blockIdx.y * 128;
    const int n0 = blockIdx.x * 128;

    const int lrow = tid >> 2;
    const int lch = (tid & 3) * 8;
    const __half* gp[3] = {
        Ah + (size_t)(m0 + lrow) * CD + lch,
        Al + (size_t)(m0 + lrow) * CD + lch,
        Wh + (size_t)(n0 + lrow) * CD + lch};
    const uint32_t s_off = (uint32_t)(lrow * TSTRIDE + lch) * 2;

    const int lrow_a = (lane & 7) + ((lane >> 3) & 1) * 8;
    const int kca = (lane >> 4) * 8;
    const int lrow_b = (lane & 7) + (lane >> 4) * 8;
    const int kcb = ((lane >> 3) & 1) * 8;

    float acc[2][8][4];
    #pragma unroll
    for (int i = 0; i < 2; i++)
        #pragma unroll
        for (int j = 0; j < 8; j++)
            #pragma unroll
            for (int q = 0; q < 4; q++) acc[i][j][q] = 0.f;

    auto load_stage = [&](int s, int k0) {
        uint32_t so = sbase + (uint32_t)(s * STAGE3_H) * 2;
        #pragma unroll
        for (int t = 0; t < 3; t++) {
            const __half* g = gp[t] + k0;
            uint32_t sa = so + (uint32_t)(t * TILE_H) * 2 + s_off;
            cp_async16(sa, g);
            cp_async16(sa + 64 * TSTRIDE * 2, g + (size_t)64 * CD);
        }
    };

    load_stage(0, 0);
    cp_commit();

    const int NIT = CD / 32;
    for (int it = 0; it < NIT; it++) {
        cp_wait0();
        __syncthreads();
        if (it + 1 < NIT) {
            load_stage((it + 1) & 1, (it + 1) * 32);
            cp_commit();
        }
        uint32_t so = sbase + (uint32_t)((it & 1) * STAGE3_H) * 2;
        #pragma unroll
        for (int ks = 0; ks < 2; ks++) {
            const int k0h = ks * 16;
            uint32_t ah[2][4], al[2][4];
            #pragma unroll
            for (int mt = 0; mt < 2; mt++) {
                int row = wm * 32 + mt * 16 + lrow_a;
                uint32_t a = so + (uint32_t)(row * TSTRIDE + k0h + kca) * 2;
                ldsm4(ah[mt], a);
                ldsm4(al[mt], a + TILE_H * 2);
            }
            uint32_t bw[4][4];
            #pragma unroll
            for (int j = 0; j < 4; j++) {
                int nr = wn * 64 + j * 16 + lrow_b;
                ldsm4(bw[j], so + (uint32_t)(2 * TILE_H + nr * TSTRIDE + k0h + kcb) * 2);
            }
            #pragma unroll
            for (int mt = 0; mt < 2; mt++)
                #pragma unroll
                for (int j = 0; j < 4; j++) {
                    mma16816(acc[mt][2 * j],     ah[mt], bw[j][0], bw[j][1]);
                    mma16816(acc[mt][2 * j + 1], ah[mt], bw[j][2], bw[j][3]);
                    mma16816(acc[mt][2 * j],     al[mt], bw[j][0], bw[j][1]);
                    mma16816(acc[mt][2 * j + 1], al[mt], bw[j][2], bw[j][3]);
                }
        }
    }

    const int cr = lane >> 2, cc = (lane & 3) * 2;
    #pragma unroll
    for (int mt = 0; mt < 2; mt++) {
        int r = m0 + wm * 32 + mt * 16 + cr;
        #pragma unroll
        for (int nt = 0; nt < 8; nt++) {
            int col = n0 + wn * 64 + nt * 8 + cc;
            *(float2*)&C[(size_t)r * CD + col] =
                make_float2(acc[mt][nt][0], acc[mt][nt][1]);
            *(float2*)&C[(size_t)(r + 8) * CD + col] =
                make_float2(acc[mt][nt][2], acc[mt][nt][3]);
        }
    }
}

// ---------------------------------------------------------------------------
// Flash attention (causal), fp16 tensor cores.
// Q split (Qh+Ql), K single, V single, P split in-register.
// CTA = 128 q-rows (8 warps x 16), KV tile 64, double-buffered cp.async.
// (unchanged from Round 11 — proven at 715.9 us)
// ---------------------------------------------------------------------------
#define ATS 72                     // smem row stride (halves)
#define ATILE (64 * ATS)           // halves per 64-row tile
#define ASTAGE (2 * ATILE)         // Kh, Vh
#define ATT_SMEM (2 * ASTAGE * 2)  // 36864 bytes

__global__ void __launch_bounds__(256, 1) attn_mma(
    const __half* __restrict__ Qh, const __half* __restrict__ Ql,
    const __half* __restrict__ Kh, const __half* __restrict__ Vh,
    __half* __restrict__ Oh, __half* __restrict__ Ol) {
    extern __shared__ __align__(16) __half sm_a[];
    const uint32_t sb = (uint32_t)__cvta_generic_to_shared(sm_a);
    const int tid = threadIdx.x;
    const int lane = tid & 31, warp = tid >> 5;
    const int qb = gridDim.x - 1 - blockIdx.x;     // heavy blocks first
    const int i0 = qb * 128;
    const int bh = blockIdx.y;
    const int b = bh >> 4, h = bh & 15;
    const size_t grow = (size_t)b * TD;
    const int gcol = h * HD;

    const int lra = (lane & 7) + ((lane >> 3) & 1) * 8;
    const int kca = (lane >> 4) * 8;
    const int lrb = (lane & 7) + (lane >> 4) * 8;
    const int kcb = ((lane >> 3) & 1) * 8;

    // ---- stage Q (128 x 64 hi+lo) across the whole smem buffer ----
    {
        #pragma unroll
        for (int k = 0; k < 4; k++) {
            int c = tid + k * 256;                 // 1024 chunks
            int row = c >> 3, colh = (c & 7) * 8;
            size_t g = (grow + i0 + row) * CD + gcol + colh;
            uint32_t sa = sb + (uint32_t)(row * ATS + colh) * 2;
            cp_async16(sa, Qh + g);
            cp_async16(sa + 2 * ATILE * 2, Ql + g);
        }
        cp_commit();
    }
    cp_wait0();
    __syncthreads();

    // ---- Q fragments (must complete before any KV load overwrites smem) ----
    uint32_t qfh[4][4], qfl[4][4];
    {
        int row = warp * 16 + lra;
        #pragma unroll
        for (int kt = 0; kt < 4; kt++) {
            uint32_t a = sb + (uint32_t)(row * ATS + kt * 16 + kca) * 2;
            ldsm4(qfh[kt], a);
            ldsm4(qfl[kt], a + 2 * ATILE * 2);
        }
    }
    __syncthreads();   // all warps done reading Q

    const int nit = qb * 2 + 2;

    auto load_kv = [&](int it) {
        uint32_t so = sb + (uint32_t)(((it + 1) & 1) * ASTAGE) * 2;
        int j0 = it * 64;
        #pragma unroll
        for (int k = 0; k < 2; k++) {
            int c = tid + k * 256;                 // 512 chunks per tile
            int row = c >> 3, colh = (c & 7) * 8;
            size_t g = (grow + j0 + row) * CD + gcol + colh;
            uint32_t sa = so + (uint32_t)(row * ATS + colh) * 2;
            cp_async16(sa, Kh + g);
            cp_async16(sa + ATILE * 2, Vh + g);
        }
        cp_commit();
    };

    load_kv(0);

    float o[8][4];
    #pragma unroll
    for (int j = 0; j < 8; j++)
        #pragma unroll
        for (int q = 0; q < 4; q++) o[j][q] = 0.f;
    float m0r = -1e30f, m1r = -1e30f, l0r = 0.f, l1r = 0.f;

    const int wrow = i0 + warp * 16;

    for (int it = 0; it < nit; it++) {
        cp_wait0();
        __syncthreads();
        if (it + 1 < nit) load_kv(it + 1);
        uint32_t so = sb + (uint32_t)(((it + 1) & 1) * ASTAGE) * 2;
        const int j0 = it * 64;

        // ---- S = Q K^T ----
        float s[8][4];
        #pragma unroll
        for (int j = 0; j < 8; j++)
            #pragma unroll
            for (int q = 0; q < 4; q++) s[j][q] = 0.f;

        #pragma unroll
        for (int kt = 0; kt < 4; kt++) {
            #pragma unroll
            for (int jp = 0; jp < 4; jp++) {
                uint32_t a = so + (uint32_t)((jp * 16 + lrb) * ATS + kt * 16 + kcb) * 2;
                uint32_t b4[4];
                ldsm4(b4, a);
                mma16816(s[2 * jp],     qfh[kt], b4[0], b4[1]);
                mma16816(s[2 * jp + 1], qfh[kt], b4[2], b4[3]);
                mma16816(s[2 * jp],     qfl[kt], b4[0], b4[1]);
                mma16816(s[2 * jp + 1], qfl[kt], b4[2], b4[3]);
            }
        }

        // ---- scale + causal mask ----
        const int r0 = wrow + (lane >> 2);
        const int r1 = r0 + 8;
        const bool domask = (j0 + 63) > wrow;
        #pragma unroll
        for (int j = 0; j < 8; j++) {
            int c0 = j0 + j * 8 + (lane & 3) * 2;
            #pragma unroll
            for (int q = 0; q < 4; q++) {
                float sv = s[j][q] * 0.125f;
                if (domask) {
                    int col = c0 + (q & 1);
                    int row = (q < 2) ? r0 : r1;
                    if (col > row) sv = -1e30f;
                }
                s[j][q] = sv;
            }
        }

        // ---- online softmax ----
        float mx0 = -1e30f, mx1 = -1e30f;
        #pragma unroll
        for (int j = 0; j < 8; j++) {
            mx0 = fmaxf(mx0, fmaxf(s[j][0], s[j][1]));
            mx1 = fmaxf(mx1, fmaxf(s[j][2], s[j][3]));
        }
        mx0 = fmaxf(mx0, __shfl_xor_sync(0xffffffffu, mx0, 1));
        mx0 = fmaxf(mx0, __shfl_xor_sync(0xffffffffu, mx0, 2));
        mx1 = fmaxf(mx1, __shfl_xor_sync(0xffffffffu, mx1, 1));
        mx1 = fmaxf(mx1, __shfl_xor_sync(0xffffffffu, mx1, 2));
        float mn0 = fmaxf(m0r, mx0), mn1 = fmaxf(m1r, mx1);
        float corr0 = __expf(m0r - mn0), corr1 = __expf(m1r - mn1);
        float rs0 = 0.f, rs1 = 0.f;
        #pragma unroll
        for (int j = 0; j < 8; j++) {
            s[j][0] = __expf(s[j][0] - mn0);
            s[j][1] = __expf(s[j][1] - mn0);
            s[j][2] = __expf(s[j][2] - mn1);
            s[j][3] = __expf(s[j][3] - mn1);
            rs0 += s[j][0] + s[j][1];
            rs1 += s[j][2] + s[j][3];
        }
        rs0 += __shfl_xor_sync(0xffffffffu, rs0, 1);
        rs0 += __shfl_xor_sync(0xffffffffu, rs0, 2);
        rs1 += __shfl_xor_sync(0xffffffffu, rs1, 1);
        rs1 += __shfl_xor_sync(0xffffffffu, rs1, 2);
        l0r = l0r * corr0 + rs0;
        l1r = l1r * corr1 + rs1;
        m0r = mn0; m1r = mn1;
        #pragma unroll
        for (int j = 0; j < 8; j++) {
            o[j][0] *= corr0; o[j][1] *= corr0;
            o[j][2] *= corr1; o[j][3] *= corr1;
        }

        // ---- O += P V (P split, V single) ----
        #pragma unroll
        for (int kt = 0; kt < 4; kt++) {
            uint32_t ph[4], pl[4];
            pack_hilo(s[2 * kt][0],     s[2 * kt][1],     ph[0], pl[0]);
            pack_hilo(s[2 * kt][2],     s[2 * kt][3],     ph[1], pl[1]);
            pack_hilo(s[2 * kt + 1][0], s[2 * kt + 1][1], ph[2], pl[2]);
            pack_hilo(s[2 * kt + 1][2], s[2 * kt + 1][3], ph[3], pl[3]);
            #pragma unroll
            for (int dn = 0; dn < 4; dn++) {
                uint32_t a = so + (uint32_t)(ATILE + (kt * 16 + lra) * ATS +
                                             dn * 16 + kca) * 2;
                uint32_t v4[4];
                ldsm4t(v4, a);
                mma16816(o[2 * dn],     ph, v4[0], v4[1]);
                mma16816(o[2 * dn + 1], ph, v4[2], v4[3]);
                mma16816(o[2 * dn],     pl, v4[0], v4[1]);
                mma16816(o[2 * dn + 1], pl, v4[2], v4[3]);
            }
        }
    }

    // ---- epilogue: normalize and write hi/lo O ----
    const float il0 = 1.0f / l0r, il1 = 1.0f / l1r;
    const int r0 = i0 + warp * 16 + (lane >> 2);
    #pragma unroll
    for (int j = 0; j < 8; j++) {
        int col = gcol + j * 8 + (lane & 3) * 2;
        uint32_t h0, l0, h1, l1;
        pack_hilo(o[j][0] * il0, o[j][1] * il0, h0, l0);
        pack_hilo(o[j][2] * il1, o[j][3] * il1, h1, l1);
        *(uint32_t*)&Oh[(grow + r0) * CD + col] = h0;
        *(uint32_t*)&Ol[(grow + r0) * CD + col] = l0;
        *(uint32_t*)&Oh[(grow + r0 + 8) * CD + col] = h1;
        *(uint32_t*)&Ol[(grow + r0 + 8) * CD + col] = l1;
    }
}

// ---------------------------------------------------------------------------

extern "C" void kernel_launch(void* const* d_in, const int* in_sizes, int n_in,
                              void* d_out, int out_size) {
    const float* x  = (const float*)d_in[0];
    const float* Wq = (const float*)d_in[1];
    const float* Wk = (const float*)d_in[2];
    const float* Wv = (const float*)d_in[3];
    const float* Wo = (const float*)d_in[4];
    float* out = (float*)d_out;

    __half *xh, *qh, *ql, *kh, *vh, *oh, *ol, *wh;
    cudaGetSymbolAddress((void**)&xh, g_xh);
    cudaGetSymbolAddress((void**)&qh, g_qh);
    cudaGetSymbolAddress((void**)&ql, g_ql);
    cudaGetSymbolAddress((void**)&kh, g_kh);
    cudaGetSymbolAddress((void**)&vh, g_vh);
    cudaGetSymbolAddress((void**)&oh, g_oh);
    cudaGetSymbolAddress((void**)&ol, g_ol);
    cudaGetSymbolAddress((void**)&wh, g_wh);

    cudaFuncSetAttribute(gemm_qkv,
                         cudaFuncAttributeMaxDynamicSharedMemorySize, QSMEM);
    cudaFuncSetAttribute(gemm_wo,
                         cudaFuncAttributeMaxDynamicSharedMemorySize, WSMEM);
    cudaFuncSetAttribute(attn_mma,
                         cudaFuncAttributeMaxDynamicSharedMemorySize, ATT_SMEM);

    const size_t CC = (size_t)CD * CD;
    const int n4x = MD * CD / 4;

    conv_kernel<<<n4x / 256, 256>>>(x, xh, n4x);
    conv4_kernel<<<4096, 256>>>(Wq, Wk, Wv, Wo, wh);

    gemm_qkv<<<dim3(24, MD / 128), 256, QSMEM>>>(xh, wh, qh, ql, kh, vh);

    attn_mma<<<dim3(TD / 128, BD * NH), 256, ATT_SMEM>>>(qh, ql, kh, vh, oh, ol);

    gemm_wo<<<dim3(CD / 128, MD / 128), 256, WSMEM>>>(oh, ol, wh + 3 * CC, out);
}

// round 14
// speedup vs baseline: 7.1094x; 1.2054x over previous
#include <cuda_runtime.h>
#include <cuda_fp16.h>
#include <cstdint>

#define CD 1024
#define BD 4
#define TD 2048
#define NH 16
#define HD 64
#define MD (BD*TD)   // 8192 rows

// Scratch (__device__ globals; allocation-free rule). fp16.
__device__ __half g_xh[(size_t)MD * CD];
__device__ __half g_qh[(size_t)MD * CD];
__device__ __half g_kh[(size_t)MD * CD];
__device__ __half g_vh[(size_t)MD * CD];
__device__ __half g_oh[(size_t)MD * CD];
__device__ __half g_ol[(size_t)MD * CD];
__device__ __half g_wh[4ull * CD * CD];

// ---------------------------------------------------------------------------
// helpers
// ---------------------------------------------------------------------------
__device__ __forceinline__ void cp_async16(uint32_t s, const void* g) {
    asm volatile("cp.async.cg.shared.global [%0], [%1], 16;\n" :: "r"(s), "l"(g));
}
__device__ __forceinline__ void cp_commit() {
    asm volatile("cp.async.commit_group;\n");
}
__device__ __forceinline__ void cp_wait0() {
    asm volatile("cp.async.wait_group 0;\n");
}
__device__ __forceinline__ void ldsm4(uint32_t* r, uint32_t a) {
    asm volatile("ldmatrix.sync.aligned.m8n8.x4.shared.b16 {%0,%1,%2,%3}, [%4];\n"
                 : "=r"(r[0]), "=r"(r[1]), "=r"(r[2]), "=r"(r[3]) : "r"(a));
}
__device__ __forceinline__ void ldsm4t(uint32_t* r, uint32_t a) {
    asm volatile("ldmatrix.sync.aligned.m8n8.x4.trans.shared.b16 {%0,%1,%2,%3}, [%4];\n"
                 : "=r"(r[0]), "=r"(r[1]), "=r"(r[2]), "=r"(r[3]) : "r"(a));
}
__device__ __forceinline__ void mma16816(float* c, const uint32_t* a,
                                         uint32_t b0, uint32_t b1) {
    asm volatile(
        "mma.sync.aligned.m16n8k16.row.col.f32.f16.f16.f32 "
        "{%0,%1,%2,%3},{%4,%5,%6,%7},{%8,%9},{%0,%1,%2,%3};\n"
        : "+f"(c[0]), "+f"(c[1]), "+f"(c[2]), "+f"(c[3])
        : "r"(a[0]), "r"(a[1]), "r"(a[2]), "r"(a[3]), "r"(b0), "r"(b1));
}
// pack two floats as fp16 hi pair + lo pair (low half = first arg)
__device__ __forceinline__ void pack_hilo(float a, float b, uint32_t& h, uint32_t& l) {
    __half ha = __float2half_rn(a), hb = __float2half_rn(b);
    __half2 H = __halves2half2(ha, hb);
    __half2 L = __halves2half2(__float2half_rn(a - __half2float(ha)),
                               __float2half_rn(b - __half2float(hb)));
    h = *reinterpret_cast<uint32_t*>(&H);
    l = *reinterpret_cast<uint32_t*>(&L);
}
__device__ __forceinline__ uint32_t pack_f16(float a, float b) {
    __half2 v = __floats2half2_rn(a, b);
    return *reinterpret_cast<uint32_t*>(&v);
}

// ---------------------------------------------------------------------------
// fp32 -> fp16 converts: x (single tensor) and all four weights (fused).
// ---------------------------------------------------------------------------
__global__ void conv_kernel(const float* __restrict__ in,
                            __half* __restrict__ out, int n4) {
    int i = blockIdx.x * blockDim.x + threadIdx.x;
    if (i >= n4) return;
    float4 v = ((const float4*)in)[i];
    ((uint32_t*)out)[2 * i]     = pack_f16(v.x, v.y);
    ((uint32_t*)out)[2 * i + 1] = pack_f16(v.z, v.w);
}
// 4 weights, 1024 blocks each (CC/4 = 262144 chunks = 1024 * 256)
__global__ void conv4_kernel(const float* __restrict__ w0,
                             const float* __restrict__ w1,
                             const float* __restrict__ w2,
                             const float* __restrict__ w3,
                             __half* __restrict__ out) {
    const int which = blockIdx.x >> 10;
    const int j = (blockIdx.x & 1023) * 256 + threadIdx.x;
    const float* in = (which == 0) ? w0 : (which == 1) ? w1 :
                      (which == 2) ? w2 : w3;
    float4 v = ((const float4*)in)[j];
    __half* o = out + (size_t)which * CD * CD;
    ((uint32_t*)o)[2 * j]     = pack_f16(v.x, v.y);
    ((uint32_t*)o)[2 * j + 1] = pack_f16(v.z, v.w);
}

// ---------------------------------------------------------------------------
// Fused QKV GEMM, plain fp16 (1 MMA/step). which = blockIdx.x>>3 selects
// Q/K/V; all outputs single fp16.
// CTA 128x128x32, 8 warps (warp tile 32x64), cp.async double buffer.
// ---------------------------------------------------------------------------
#define TSTRIDE 40
#define TILE_H (128 * TSTRIDE)
#define STAGE2_H (2 * TILE_H)          // X, W
#define QSMEM (2 * STAGE2_H * 2)       // 40960 bytes

__global__ void __launch_bounds__(256, 2) gemm_qkv(
    const __half* __restrict__ X, const __half* __restrict__ Wall,
    __half* __restrict__ Qh, __half* __restrict__ Kh, __half* __restrict__ Vh) {
    extern __shared__ __align__(16) __half sm_g[];
    const uint32_t sbase = (uint32_t)__cvta_generic_to_shared(sm_g);
    const int tid = threadIdx.x;
    const int lane = tid & 31, warp = tid >> 5;
    const int wm = warp >> 1, wn = warp & 1;
    const int which = blockIdx.x >> 3;
    const int n0 = (blockIdx.x & 7) * 128;
    const int m0 = blockIdx.y * 128;

    const int lrow = tid >> 2;
    const int lch = (tid & 3) * 8;
    const __half* gp[2] = {
        X + (size_t)(m0 + lrow) * CD + lch,
        Wall + (size_t)which * CD * CD + (size_t)(n0 + lrow) * CD + lch};
    const uint32_t s_off = (uint32_t)(lrow * TSTRIDE + lch) * 2;

    const int lrow_a = (lane & 7) + ((lane >> 3) & 1) * 8;
    const int kca = (lane >> 4) * 8;
    const int lrow_b = (lane & 7) + (lane >> 4) * 8;
    const int kcb = ((lane >> 3) & 1) * 8;

    float acc[2][8][4];
    #pragma unroll
    for (int i = 0; i < 2; i++)
        #pragma unroll
        for (int j = 0; j < 8; j++)
            #pragma unroll
            for (int q = 0; q < 4; q++) acc[i][j][q] = 0.f;

    auto load_stage = [&](int s, int k0) {
        uint32_t so = sbase + (uint32_t)(s * STAGE2_H) * 2;
        #pragma unroll
        for (int t = 0; t < 2; t++) {
            const __half* g = gp[t] + k0;
            uint32_t sa = so + (uint32_t)(t * TILE_H) * 2 + s_off;
            cp_async16(sa, g);
            cp_async16(sa + 64 * TSTRIDE * 2, g + (size_t)64 * CD);
        }
    };

    load_stage(0, 0);
    cp_commit();

    const int NIT = CD / 32;
    for (int it = 0; it < NIT; it++) {
        cp_wait0();
        __syncthreads();
        if (it + 1 < NIT) {
            load_stage((it + 1) & 1, (it + 1) * 32);
            cp_commit();
        }
        uint32_t so = sbase + (uint32_t)((it & 1) * STAGE2_H) * 2;
        #pragma unroll
        for (int ks = 0; ks < 2; ks++) {
            const int k0h = ks * 16;
            uint32_t ah[2][4];
            #pragma unroll
            for (int mt = 0; mt < 2; mt++) {
                int row = wm * 32 + mt * 16 + lrow_a;
                ldsm4(ah[mt], so + (uint32_t)(row * TSTRIDE + k0h + kca) * 2);
            }
            uint32_t bw[4][4];
            #pragma unroll
            for (int j = 0; j < 4; j++) {
                int nr = wn * 64 + j * 16 + lrow_b;
                ldsm4(bw[j], so + (uint32_t)(TILE_H + nr * TSTRIDE + k0h + kcb) * 2);
            }
            #pragma unroll
            for (int mt = 0; mt < 2; mt++)
                #pragma unroll
                for (int j = 0; j < 4; j++) {
                    mma16816(acc[mt][2 * j],     ah[mt], bw[j][0], bw[j][1]);
                    mma16816(acc[mt][2 * j + 1], ah[mt], bw[j][2], bw[j][3]);
                }
        }
    }

    __half* D = (which == 0) ? Qh : (which == 1) ? Kh : Vh;
    const int cr = lane >> 2, cc = (lane & 3) * 2;
    #pragma unroll
    for (int mt = 0; mt < 2; mt++) {
        int r = m0 + wm * 32 + mt * 16 + cr;
        #pragma unroll
        for (int nt = 0; nt < 8; nt++) {
            int col = n0 + wn * 64 + nt * 8 + cc;
            *(uint32_t*)&D[(size_t)r * CD + col] =
                pack_f16(acc[mt][nt][0], acc[mt][nt][1]);
            *(uint32_t*)&D[(size_t)(r + 8) * CD + col] =
                pack_f16(acc[mt][nt][2], acc[mt][nt][3]);
        }
    }
}

// ---------------------------------------------------------------------------
// Output GEMM: out = O@Wo^T, O = 2-term fp16 split (2 MMAs/step), fp32 out.
// CTA 128x128x32, 3-tile stages (Oh, Ol, Wo), cp.async double buffer.
// ---------------------------------------------------------------------------
#define STAGE3_H (3 * TILE_H)
#define WSMEM (2 * STAGE3_H * 2)       // 61440 bytes

__global__ void __launch_bounds__(256, 2) gemm_wo(
    const __half* __restrict__ Ah, const __half* __restrict__ Al,
    const __half* __restrict__ Wh, float* __restrict__ C) {
    extern __shared__ __align__(16) __half sm_g[];
    const uint32_t sbase = (uint32_t)__cvta_generic_to_shared(sm_g);
    const int tid = threadIdx.x;
    const int lane = tid & 31, warp = tid >> 5;
    const int wm = warp >> 1, wn = warp & 1;
    const int m0 = blockIdx.y * 128;
    const int n0 = blockIdx.x * 128;

    const int lrow = tid >> 2;
    const int lch = (tid & 3) * 8;
    const __half* gp[3] = {
        Ah + (size_t)(m0 + lrow) * CD + lch,
        Al + (size_t)(m0 + lrow) * CD + lch,
        Wh + (size_t)(n0 + lrow) * CD + lch};
    const uint32_t s_off = (uint32_t)(lrow * TSTRIDE + lch) * 2;

    const int lrow_a = (lane & 7) + ((lane >> 3) & 1) * 8;
    const int kca = (lane >> 4) * 8;
    const int lrow_b = (lane & 7) + (lane >> 4) * 8;
    const int kcb = ((lane >> 3) & 1) * 8;

    float acc[2][8][4];
    #pragma unroll
    for (int i = 0; i < 2; i++)
        #pragma unroll
        for (int j = 0; j < 8; j++)
            #pragma unroll
            for (int q = 0; q < 4; q++) acc[i][j][q] = 0.f;

    auto load_stage = [&](int s, int k0) {
        uint32_t so = sbase + (uint32_t)(s * STAGE3_H) * 2;
        #pragma unroll
        for (int t = 0; t < 3; t++) {
            const __half* g = gp[t] + k0;
            uint32_t sa = so + (uint32_t)(t * TILE_H) * 2 + s_off;
            cp_async16(sa, g);
            cp_async16(sa + 64 * TSTRIDE * 2, g + (size_t)64 * CD);
        }
    };

    load_stage(0, 0);
    cp_commit();

    const int NIT = CD / 32;
    for (int it = 0; it < NIT; it++) {
        cp_wait0();
        __syncthreads();
        if (it + 1 < NIT) {
            load_stage((it + 1) & 1, (it + 1) * 32);
            cp_commit();
        }
        uint32_t so = sbase + (uint32_t)((it & 1) * STAGE3_H) * 2;
        #pragma unroll
        for (int ks = 0; ks < 2; ks++) {
            const int k0h = ks * 16;
            uint32_t ah[2][4], al[2][4];
            #pragma unroll
            for (int mt = 0; mt < 2; mt++) {
                int row = wm * 32 + mt * 16 + lrow_a;
                uint32_t a = so + (uint32_t)(row * TSTRIDE + k0h + kca) * 2;
                ldsm4(ah[mt], a);
                ldsm4(al[mt], a + TILE_H * 2);
            }
            uint32_t bw[4][4];
            #pragma unroll
            for (int j = 0; j < 4; j++) {
                int nr = wn * 64 + j * 16 + lrow_b;
                ldsm4(bw[j], so + (uint32_t)(2 * TILE_H + nr * TSTRIDE + k0h + kcb) * 2);
            }
            #pragma unroll
            for (int mt = 0; mt < 2; mt++)
                #pragma unroll
                for (int j = 0; j < 4; j++) {
                    mma16816(acc[mt][2 * j],     ah[mt], bw[j][0], bw[j][1]);
                    mma16816(acc[mt][2 * j + 1], ah[mt], bw[j][2], bw[j][3]);
                    mma16816(acc[mt][2 * j],     al[mt], bw[j][0], bw[j][1]);
                    mma16816(acc[mt][2 * j + 1], al[mt], bw[j][2], bw[j][3]);
                }
        }
    }

    const int cr = lane >> 2, cc = (lane & 3) * 2;
    #pragma unroll
    for (int mt = 0; mt < 2; mt++) {
        int r = m0 + wm * 32 + mt * 16 + cr;
        #pragma unroll
        for (int nt = 0; nt < 8; nt++) {
            int col = n0 + wn * 64 + nt * 8 + cc;
            *(float2*)&C[(size_t)r * CD + col] =
                make_float2(acc[mt][nt][0], acc[mt][nt][1]);
            *(float2*)&C[(size_t)(r + 8) * CD + col] =
                make_float2(acc[mt][nt][2], acc[mt][nt][3]);
        }
    }
}

// ---------------------------------------------------------------------------
// Flash attention (causal), fp16 tensor cores. Q/K/V/P all single fp16,
// fp32 accumulators; O emitted as exact hi/lo split for the Wo GEMM.
// CTA = 128 q-rows (8 warps x 16), KV tile 64, double-buffered cp.async,
// 2 CTAs/SM (launch_bounds) for latency hiding.
// ---------------------------------------------------------------------------
#define ATS 72                     // smem row stride (halves)
#define ATILE (64 * ATS)           // halves per 64-row tile
#define ASTAGE (2 * ATILE)         // Kh, Vh
#define ATT_SMEM (2 * ASTAGE * 2)  // 36864 bytes

__global__ void __launch_bounds__(256, 2) attn_mma(
    const __half* __restrict__ Qh, const __half* __restrict__ Kh,
    const __half* __restrict__ Vh,
    __half* __restrict__ Oh, __half* __restrict__ Ol) {
    extern __shared__ __align__(16) __half sm_a[];
    const uint32_t sb = (uint32_t)__cvta_generic_to_shared(sm_a);
    const int tid = threadIdx.x;
    const int lane = tid & 31, warp = tid >> 5;
    const int qb = gridDim.x - 1 - blockIdx.x;     // heavy blocks first
    const int i0 = qb * 128;
    const int bh = blockIdx.y;
    const int b = bh >> 4, h = bh & 15;
    const size_t grow = (size_t)b * TD;
    const int gcol = h * HD;

    const int lra = (lane & 7) + ((lane >> 3) & 1) * 8;
    const int kca = (lane >> 4) * 8;
    const int lrb = (lane & 7) + (lane >> 4) * 8;
    const int kcb = ((lane >> 3) & 1) * 8;

    const int nit = qb * 2 + 2;

    auto load_kv = [&](int it) {
        uint32_t so = sb + (uint32_t)(((it + 1) & 1) * ASTAGE) * 2;
        int j0 = it * 64;
        #pragma unroll
        for (int k = 0; k < 2; k++) {
            int c = tid + k * 256;                 // 512 chunks per tile
            int row = c >> 3, colh = (c & 7) * 8;
            size_t g = (grow + j0 + row) * CD + gcol + colh;
            uint32_t sa = so + (uint32_t)(row * ATS + colh) * 2;
            cp_async16(sa, Kh + g);
            cp_async16(sa + ATILE * 2, Vh + g);
        }
        cp_commit();
    };

    // ---- stage Q (128 x 64) into stage 0 (rows 0..127 x ATS) ----
    {
        #pragma unroll
        for (int k = 0; k < 4; k++) {
            int c = tid + k * 256;                 // 1024 chunks
            int row = c >> 3, colh = (c & 7) * 8;
            size_t g = (grow + i0 + row) * CD + gcol + colh;
            cp_async16(sb + (uint32_t)(row * ATS + colh) * 2, Qh + g);
        }
        cp_commit();
    }
    cp_wait0();
    __syncthreads();

    // KV tile 0 goes to stage 1 — disjoint from Q in stage 0, so prefetch
    // it before reading Q fragments.
    load_kv(0);

    uint32_t qf[4][4];
    {
        int row = warp * 16 + lra;
        #pragma unroll
        for (int kt = 0; kt < 4; kt++)
            ldsm4(qf[kt], sb + (uint32_t)(row * ATS + kt * 16 + kca) * 2);
    }
    __syncthreads();   // all warps done reading Q before iter-0 loads stage 0

    float o[8][4];
    #pragma unroll
    for (int j = 0; j < 8; j++)
        #pragma unroll
        for (int q = 0; q < 4; q++) o[j][q] = 0.f;
    float m0r = -1e30f, m1r = -1e30f, l0r = 0.f, l1r = 0.f;

    const int wrow = i0 + warp * 16;

    for (int it = 0; it < nit; it++) {
        cp_wait0();
        __syncthreads();
        if (it + 1 < nit) load_kv(it + 1);
        uint32_t so = sb + (uint32_t)(((it + 1) & 1) * ASTAGE) * 2;
        const int j0 = it * 64;

        // ---- S = Q K^T ----
        float s[8][4];
        #pragma unroll
        for (int j = 0; j < 8; j++)
            #pragma unroll
            for (int q = 0; q < 4; q++) s[j][q] = 0.f;

        #pragma unroll
        for (int kt = 0; kt < 4; kt++) {
            #pragma unroll
            for (int jp = 0; jp < 4; jp++) {
                uint32_t a = so + (uint32_t)((jp * 16 + lrb) * ATS + kt * 16 + kcb) * 2;
                uint32_t b4[4];
                ldsm4(b4, a);
                mma16816(s[2 * jp],     qf[kt], b4[0], b4[1]);
                mma16816(s[2 * jp + 1], qf[kt], b4[2], b4[3]);
            }
        }

        // ---- scale + causal mask ----
        const int r0 = wrow + (lane >> 2);
        const int r1 = r0 + 8;
        const bool domask = (j0 + 63) > wrow;
        #pragma unroll
        for (int j = 0; j < 8; j++) {
            int c0 = j0 + j * 8 + (lane & 3) * 2;
            #pragma unroll
            for (int q = 0; q < 4; q++) {
                float sv = s[j][q] * 0.125f;
                if (domask) {
                    int col = c0 + (q & 1);
                    int row = (q < 2) ? r0 : r1;
                    if (col > row) sv = -1e30f;
                }
                s[j][q] = sv;
            }
        }

        // ---- online softmax ----
        float mx0 = -1e30f, mx1 = -1e30f;
        #pragma unroll
        for (int j = 0; j < 8; j++) {
            mx0 = fmaxf(mx0, fmaxf(s[j][0], s[j][1]));
            mx1 = fmaxf(mx1, fmaxf(s[j][2], s[j][3]));
        }
        mx0 = fmaxf(mx0, __shfl_xor_sync(0xffffffffu, mx0, 1));
        mx0 = fmaxf(mx0, __shfl_xor_sync(0xffffffffu, mx0, 2));
        mx1 = fmaxf(mx1, __shfl_xor_sync(0xffffffffu, mx1, 1));
        mx1 = fmaxf(mx1, __shfl_xor_sync(0xffffffffu, mx1, 2));
        float mn0 = fmaxf(m0r, mx0), mn1 = fmaxf(m1r, mx1);
        float corr0 = __expf(m0r - mn0), corr1 = __expf(m1r - mn1);
        float rs0 = 0.f, rs1 = 0.f;
        #pragma unroll
        for (int j = 0; j < 8; j++) {
            s[j][0] = __expf(s[j][0] - mn0);
            s[j][1] = __expf(s[j][1] - mn0);
            s[j][2] = __expf(s[j][2] - mn1);
            s[j][3] = __expf(s[j][3] - mn1);
            rs0 += s[j][0] + s[j][1];
            rs1 += s[j][2] + s[j][3];
        }
        rs0 += __shfl_xor_sync(0xffffffffu, rs0, 1);
        rs0 += __shfl_xor_sync(0xffffffffu, rs0, 2);
        rs1 += __shfl_xor_sync(0xffffffffu, rs1, 1);
        rs1 += __shfl_xor_sync(0xffffffffu, rs1, 2);
        l0r = l0r * corr0 + rs0;
        l1r = l1r * corr1 + rs1;
        m0r = mn0; m1r = mn1;
        #pragma unroll
        for (int j = 0; j < 8; j++) {
            o[j][0] *= corr0; o[j][1] *= corr0;
            o[j][2] *= corr1; o[j][3] *= corr1;
        }

        // ---- O += P V (both single fp16) ----
        #pragma unroll
        for (int kt = 0; kt < 4; kt++) {
            uint32_t ph[4];
            ph[0] = pack_f16(s[2 * kt][0],     s[2 * kt][1]);
            ph[1] = pack_f16(s[2 * kt][2],     s[2 * kt][3]);
            ph[2] = pack_f16(s[2 * kt + 1][0], s[2 * kt + 1][1]);
            ph[3] = pack_f16(s[2 * kt + 1][2], s[2 * kt + 1][3]);
            #pragma unroll
            for (int dn = 0; dn < 4; dn++) {
                uint32_t a = so + (uint32_t)(ATILE + (kt * 16 + lra) * ATS +
                                             dn * 16 + kca) * 2;
                uint32_t v4[4];
                ldsm4t(v4, a);
                mma16816(o[2 * dn],     ph, v4[0], v4[1]);
                mma16816(o[2 * dn + 1], ph, v4[2], v4[3]);
            }
        }
    }

    // ---- epilogue: normalize and write hi/lo O ----
    const float il0 = 1.0f / l0r, il1 = 1.0f / l1r;
    const int r0 = i0 + warp * 16 + (lane >> 2);
    #pragma unroll
    for (int j = 0; j < 8; j++) {
        int col = gcol + j * 8 + (lane & 3) * 2;
        uint32_t h0, l0, h1, l1;
        pack_hilo(o[j][0] * il0, o[j][1] * il0, h0, l0);
        pack_hilo(o[j][2] * il1, o[j][3] * il1, h1, l1);
        *(uint32_t*)&Oh[(grow + r0) * CD + col] = h0;
        *(uint32_t*)&Ol[(grow + r0) * CD + col] = l0;
        *(uint32_t*)&Oh[(grow + r0 + 8) * CD + col] = h1;
        *(uint32_t*)&Ol[(grow + r0 + 8) * CD + col] = l1;
    }
}

// ---------------------------------------------------------------------------

extern "C" void kernel_launch(void* const* d_in, const int* in_sizes, int n_in,
                              void* d_out, int out_size) {
    const float* x  = (const float*)d_in[0];
    const float* Wq = (const float*)d_in[1];
    const float* Wk = (const float*)d_in[2];
    const float* Wv = (const float*)d_in[3];
    const float* Wo = (const float*)d_in[4];
    float* out = (float*)d_out;

    __half *xh, *qh, *kh, *vh, *oh, *ol, *wh;
    cudaGetSymbolAddress((void**)&xh, g_xh);
    cudaGetSymbolAddress((void**)&qh, g_qh);
    cudaGetSymbolAddress((void**)&kh, g_kh);
    cudaGetSymbolAddress((void**)&vh, g_vh);
    cudaGetSymbolAddress((void**)&oh, g_oh);
    cudaGetSymbolAddress((void**)&ol, g_ol);
    cudaGetSymbolAddress((void**)&wh, g_wh);

    cudaFuncSetAttribute(gemm_qkv,
                         cudaFuncAttributeMaxDynamicSharedMemorySize, QSMEM);
    cudaFuncSetAttribute(gemm_wo,
                         cudaFuncAttributeMaxDynamicSharedMemorySize, WSMEM);
    cudaFuncSetAttribute(attn_mma,
                         cudaFuncAttributeMaxDynamicSharedMemorySize, ATT_SMEM);

    const size_t CC = (size_t)CD * CD;
    const int n4x = MD * CD / 4;

    conv_kernel<<<n4x / 256, 256>>>(x, xh, n4x);
    conv4_kernel<<<4096, 256>>>(Wq, Wk, Wv, Wo, wh);

    gemm_qkv<<<dim3(24, MD / 128), 256, QSMEM>>>(xh, wh, qh, kh, vh);

    attn_mma<<<dim3(TD / 128, BD * NH), 256, ATT_SMEM>>>(qh, kh, vh, oh, ol);

    gemm_wo<<<dim3(CD / 128, MD / 128), 256, WSMEM>>>(oh, ol, wh + 3 * CC, out);
}

// round 15
// speedup vs baseline: 8.2303x; 1.1577x over previous
#include <cuda_runtime.h>
#include <cuda_fp16.h>
#include <cstdint>

#define CD 1024
#define BD 4
#define TD 2048
#define NH 16
#define HD 64
#define MD (BD*TD)   // 8192 rows

// Scratch (__device__ globals; allocation-free rule). fp16.
__device__ __half g_xh[(size_t)MD * CD];
__device__ __half g_qh[(size_t)MD * CD];
__device__ __half g_kh[(size_t)MD * CD];
__device__ __half g_vh[(size_t)MD * CD];
__device__ __half g_oh[(size_t)MD * CD];
__device__ __half g_wh[4ull * CD * CD];

// ---------------------------------------------------------------------------
// helpers
// ---------------------------------------------------------------------------
__device__ __forceinline__ void cp_async16(uint32_t s, const void* g) {
    asm volatile("cp.async.cg.shared.global [%0], [%1], 16;\n" :: "r"(s), "l"(g));
}
__device__ __forceinline__ void cp_commit() {
    asm volatile("cp.async.commit_group;\n");
}
__device__ __forceinline__ void cp_wait0() {
    asm volatile("cp.async.wait_group 0;\n");
}
__device__ __forceinline__ void ldsm4(uint32_t* r, uint32_t a) {
    asm volatile("ldmatrix.sync.aligned.m8n8.x4.shared.b16 {%0,%1,%2,%3}, [%4];\n"
                 : "=r"(r[0]), "=r"(r[1]), "=r"(r[2]), "=r"(r[3]) : "r"(a));
}
__device__ __forceinline__ void ldsm4t(uint32_t* r, uint32_t a) {
    asm volatile("ldmatrix.sync.aligned.m8n8.x4.trans.shared.b16 {%0,%1,%2,%3}, [%4];\n"
                 : "=r"(r[0]), "=r"(r[1]), "=r"(r[2]), "=r"(r[3]) : "r"(a));
}
__device__ __forceinline__ void mma16816(float* c, const uint32_t* a,
                                         uint32_t b0, uint32_t b1) {
    asm volatile(
        "mma.sync.aligned.m16n8k16.row.col.f32.f16.f16.f32 "
        "{%0,%1,%2,%3},{%4,%5,%6,%7},{%8,%9},{%0,%1,%2,%3};\n"
        : "+f"(c[0]), "+f"(c[1]), "+f"(c[2]), "+f"(c[3])
        : "r"(a[0]), "r"(a[1]), "r"(a[2]), "r"(a[3]), "r"(b0), "r"(b1));
}
__device__ __forceinline__ uint32_t pack_f16(float a, float b) {
    __half2 v = __floats2half2_rn(a, b);
    return *reinterpret_cast<uint32_t*>(&v);
}
__device__ __forceinline__ float fexp2(float x) {
    float y;
    asm("ex2.approx.ftz.f32 %0, %1;" : "=f"(y) : "f"(x));
    return y;
}

// ---------------------------------------------------------------------------
// fp32 -> fp16 converts: x (single tensor) and all four weights (fused).
// ---------------------------------------------------------------------------
__global__ void conv_kernel(const float* __restrict__ in,
                            __half* __restrict__ out, int n4) {
    int i = blockIdx.x * blockDim.x + threadIdx.x;
    if (i >= n4) return;
    float4 v = ((const float4*)in)[i];
    ((uint32_t*)out)[2 * i]     = pack_f16(v.x, v.y);
    ((uint32_t*)out)[2 * i + 1] = pack_f16(v.z, v.w);
}
// 4 weights, 1024 blocks each (CC/4 = 262144 chunks = 1024 * 256)
__global__ void conv4_kernel(const float* __restrict__ w0,
                             const float* __restrict__ w1,
                             const float* __restrict__ w2,
                             const float* __restrict__ w3,
                             __half* __restrict__ out) {
    const int which = blockIdx.x >> 10;
    const int j = (blockIdx.x & 1023) * 256 + threadIdx.x;
    const float* in = (which == 0) ? w0 : (which == 1) ? w1 :
                      (which == 2) ? w2 : w3;
    float4 v = ((const float4*)in)[j];
    __half* o = out + (size_t)which * CD * CD;
    ((uint32_t*)o)[2 * j]     = pack_f16(v.x, v.y);
    ((uint32_t*)o)[2 * j + 1] = pack_f16(v.z, v.w);
}

// ---------------------------------------------------------------------------
// Plain fp16 GEMM (1 MMA/step), two output modes:
//   OM=0: fused QKV — blockIdx.x>>3 selects Q/K/V, fp16 out
//   OM=1: Wo        — fp32 out to the harness buffer
// CTA 128x128x32, 8 warps (warp tile 32x64), cp.async double buffer.
// ---------------------------------------------------------------------------
#define TSTRIDE 40
#define TILE_H (128 * TSTRIDE)
#define STAGE2_H (2 * TILE_H)          // A, W
#define QSMEM (2 * STAGE2_H * 2)       // 40960 bytes

template <int OM>
__global__ void __launch_bounds__(256, 2) gemm_f16(
    const __half* __restrict__ X, const __half* __restrict__ Wall,
    __half* __restrict__ Qh, __half* __restrict__ Kh, __half* __restrict__ Vh,
    float* __restrict__ C) {
    extern __shared__ __align__(16) __half sm_g[];
    const uint32_t sbase = (uint32_t)__cvta_generic_to_shared(sm_g);
    const int tid = threadIdx.x;
    const int lane = tid & 31, warp = tid >> 5;
    const int wm = warp >> 1, wn = warp & 1;
    const int which = (OM == 0) ? (blockIdx.x >> 3) : 0;
    const int n0 = (OM == 0) ? (blockIdx.x & 7) * 128 : blockIdx.x * 128;
    const int m0 = blockIdx.y * 128;

    const int lrow = tid >> 2;
    const int lch = (tid & 3) * 8;
    const __half* gp[2] = {
        X + (size_t)(m0 + lrow) * CD + lch,
        Wall + (size_t)which * CD * CD + (size_t)(n0 + lrow) * CD + lch};
    const uint32_t s_off = (uint32_t)(lrow * TSTRIDE + lch) * 2;

    const int lrow_a = (lane & 7) + ((lane >> 3) & 1) * 8;
    const int kca = (lane >> 4) * 8;
    const int lrow_b = (lane & 7) + (lane >> 4) * 8;
    const int kcb = ((lane >> 3) & 1) * 8;

    float acc[2][8][4];
    #pragma unroll
    for (int i = 0; i < 2; i++)
        #pragma unroll
        for (int j = 0; j < 8; j++)
            #pragma unroll
            for (int q = 0; q < 4; q++) acc[i][j][q] = 0.f;

    auto load_stage = [&](int s, int k0) {
        uint32_t so = sbase + (uint32_t)(s * STAGE2_H) * 2;
        #pragma unroll
        for (int t = 0; t < 2; t++) {
            const __half* g = gp[t] + k0;
            uint32_t sa = so + (uint32_t)(t * TILE_H) * 2 + s_off;
            cp_async16(sa, g);
            cp_async16(sa + 64 * TSTRIDE * 2, g + (size_t)64 * CD);
        }
    };

    load_stage(0, 0);
    cp_commit();

    const int NIT = CD / 32;
    for (int it = 0; it < NIT; it++) {
        cp_wait0();
        __syncthreads();
        if (it + 1 < NIT) {
            load_stage((it + 1) & 1, (it + 1) * 32);
            cp_commit();
        }
        uint32_t so = sbase + (uint32_t)((it & 1) * STAGE2_H) * 2;
        #pragma unroll
        for (int ks = 0; ks < 2; ks++) {
            const int k0h = ks * 16;
            uint32_t ah[2][4];
            #pragma unroll
            for (int mt = 0; mt < 2; mt++) {
                int row = wm * 32 + mt * 16 + lrow_a;
                ldsm4(ah[mt], so + (uint32_t)(row * TSTRIDE + k0h + kca) * 2);
            }
            uint32_t bw[4][4];
            #pragma unroll
            for (int j = 0; j < 4; j++) {
                int nr = wn * 64 + j * 16 + lrow_b;
                ldsm4(bw[j], so + (uint32_t)(TILE_H + nr * TSTRIDE + k0h + kcb) * 2);
            }
            #pragma unroll
            for (int mt = 0; mt < 2; mt++)
                #pragma unroll
                for (int j = 0; j < 4; j++) {
                    mma16816(acc[mt][2 * j],     ah[mt], bw[j][0], bw[j][1]);
                    mma16816(acc[mt][2 * j + 1], ah[mt], bw[j][2], bw[j][3]);
                }
        }
    }

    const int cr = lane >> 2, cc = (lane & 3) * 2;
    if (OM == 0) {
        __half* D = (which == 0) ? Qh : (which == 1) ? Kh : Vh;
        #pragma unroll
        for (int mt = 0; mt < 2; mt++) {
            int r = m0 + wm * 32 + mt * 16 + cr;
            #pragma unroll
            for (int nt = 0; nt < 8; nt++) {
                int col = n0 + wn * 64 + nt * 8 + cc;
                *(uint32_t*)&D[(size_t)r * CD + col] =
                    pack_f16(acc[mt][nt][0], acc[mt][nt][1]);
                *(uint32_t*)&D[(size_t)(r + 8) * CD + col] =
                    pack_f16(acc[mt][nt][2], acc[mt][nt][3]);
            }
        }
    } else {
        #pragma unroll
        for (int mt = 0; mt < 2; mt++) {
            int r = m0 + wm * 32 + mt * 16 + cr;
            #pragma unroll
            for (int nt = 0; nt < 8; nt++) {
                int col = n0 + wn * 64 + nt * 8 + cc;
                *(float2*)&C[(size_t)r * CD + col] =
                    make_float2(acc[mt][nt][0], acc[mt][nt][1]);
                *(float2*)&C[(size_t)(r + 8) * CD + col] =
                    make_float2(acc[mt][nt][2], acc[mt][nt][3]);
            }
        }
    }
}

// ---------------------------------------------------------------------------
// Flash attention (causal), fp16 tensor cores. Q/K/V/P/O single fp16,
// fp32 accumulators. Softmax in exp2 domain (scale folded into log2e const).
// CTA = 128 q-rows (8 warps x 16), KV tile 64, double-buffered cp.async,
// 2 CTAs/SM.
// ---------------------------------------------------------------------------
#define ATS 72                     // smem row stride (halves)
#define ATILE (64 * ATS)           // halves per 64-row tile
#define ASTAGE (2 * ATILE)         // Kh, Vh
#define ATT_SMEM (2 * ASTAGE * 2)  // 36864 bytes
#define SCL2 0.18033688f           // 0.125 * log2(e)

__global__ void __launch_bounds__(256, 2) attn_mma(
    const __half* __restrict__ Qh, const __half* __restrict__ Kh,
    const __half* __restrict__ Vh, __half* __restrict__ Oh) {
    extern __shared__ __align__(16) __half sm_a[];
    const uint32_t sb = (uint32_t)__cvta_generic_to_shared(sm_a);
    const int tid = threadIdx.x;
    const int lane = tid & 31, warp = tid >> 5;
    const int qb = gridDim.x - 1 - blockIdx.x;     // heavy blocks first
    const int i0 = qb * 128;
    const int bh = blockIdx.y;
    const int b = bh >> 4, h = bh & 15;
    const size_t grow = (size_t)b * TD;
    const int gcol = h * HD;

    const int lra = (lane & 7) + ((lane >> 3) & 1) * 8;
    const int kca = (lane >> 4) * 8;
    const int lrb = (lane & 7) + (lane >> 4) * 8;
    const int kcb = ((lane >> 3) & 1) * 8;

    const int nit = qb * 2 + 2;

    auto load_kv = [&](int it) {
        uint32_t so = sb + (uint32_t)(((it + 1) & 1) * ASTAGE) * 2;
        int j0 = it * 64;
        #pragma unroll
        for (int k = 0; k < 2; k++) {
            int c = tid + k * 256;                 // 512 chunks per tile
            int row = c >> 3, colh = (c & 7) * 8;
            size_t g = (grow + j0 + row) * CD + gcol + colh;
            uint32_t sa = so + (uint32_t)(row * ATS + colh) * 2;
            cp_async16(sa, Kh + g);
            cp_async16(sa + ATILE * 2, Vh + g);
        }
        cp_commit();
    };

    // ---- stage Q (128 x 64) into stage 0 (rows 0..127 x ATS) ----
    {
        #pragma unroll
        for (int k = 0; k < 4; k++) {
            int c = tid + k * 256;                 // 1024 chunks
            int row = c >> 3, colh = (c & 7) * 8;
            size_t g = (grow + i0 + row) * CD + gcol + colh;
            cp_async16(sb + (uint32_t)(row * ATS + colh) * 2, Qh + g);
        }
        cp_commit();
    }
    cp_wait0();
    __syncthreads();

    // KV tile 0 goes to stage 1 — disjoint from Q in stage 0.
    load_kv(0);

    uint32_t qf[4][4];
    {
        int row = warp * 16 + lra;
        #pragma unroll
        for (int kt = 0; kt < 4; kt++)
            ldsm4(qf[kt], sb + (uint32_t)(row * ATS + kt * 16 + kca) * 2);
    }
    __syncthreads();   // all warps done reading Q before iter-0 loads stage 0

    float o[8][4];
    #pragma unroll
    for (int j = 0; j < 8; j++)
        #pragma unroll
        for (int q = 0; q < 4; q++) o[j][q] = 0.f;
    float m0r = -1e30f, m1r = -1e30f, l0r = 0.f, l1r = 0.f;

    const int wrow = i0 + warp * 16;

    for (int it = 0; it < nit; it++) {
        cp_wait0();
        __syncthreads();
        if (it + 1 < nit) load_kv(it + 1);
        uint32_t so = sb + (uint32_t)(((it + 1) & 1) * ASTAGE) * 2;
        const int j0 = it * 64;

        // ---- S = Q K^T ----
        float s[8][4];
        #pragma unroll
        for (int j = 0; j < 8; j++)
            #pragma unroll
            for (int q = 0; q < 4; q++) s[j][q] = 0.f;

        #pragma unroll
        for (int kt = 0; kt < 4; kt++) {
            #pragma unroll
            for (int jp = 0; jp < 4; jp++) {
                uint32_t a = so + (uint32_t)((jp * 16 + lrb) * ATS + kt * 16 + kcb) * 2;
                uint32_t b4[4];
                ldsm4(b4, a);
                mma16816(s[2 * jp],     qf[kt], b4[0], b4[1]);
                mma16816(s[2 * jp + 1], qf[kt], b4[2], b4[3]);
            }
        }

        // ---- scale (exp2 domain) + causal mask ----
        const int r0 = wrow + (lane >> 2);
        const int r1 = r0 + 8;
        const bool domask = (j0 + 63) > wrow;
        #pragma unroll
        for (int j = 0; j < 8; j++) {
            int c0 = j0 + j * 8 + (lane & 3) * 2;
            #pragma unroll
            for (int q = 0; q < 4; q++) {
                float sv = s[j][q] * SCL2;
                if (domask) {
                    int col = c0 + (q & 1);
                    int row = (q < 2) ? r0 : r1;
                    if (col > row) sv = -1e30f;
                }
                s[j][q] = sv;
            }
        }

        // ---- online softmax (base-2) ----
        float mx0 = -1e30f, mx1 = -1e30f;
        #pragma unroll
        for (int j = 0; j < 8; j++) {
            mx0 = fmaxf(mx0, fmaxf(s[j][0], s[j][1]));
            mx1 = fmaxf(mx1, fmaxf(s[j][2], s[j][3]));
        }
        mx0 = fmaxf(mx0, __shfl_xor_sync(0xffffffffu, mx0, 1));
        mx0 = fmaxf(mx0, __shfl_xor_sync(0xffffffffu, mx0, 2));
        mx1 = fmaxf(mx1, __shfl_xor_sync(0xffffffffu, mx1, 1));
        mx1 = fmaxf(mx1, __shfl_xor_sync(0xffffffffu, mx1, 2));
        float mn0 = fmaxf(m0r, mx0), mn1 = fmaxf(m1r, mx1);
        float corr0 = fexp2(m0r - mn0), corr1 = fexp2(m1r - mn1);
        float rs0 = 0.f, rs1 = 0.f;
        #pragma unroll
        for (int j = 0; j < 8; j++) {
            s[j][0] = fexp2(s[j][0] - mn0);
            s[j][1] = fexp2(s[j][1] - mn0);
            s[j][2] = fexp2(s[j][2] - mn1);
            s[j][3] = fexp2(s[j][3] - mn1);
            rs0 += s[j][0] + s[j][1];
            rs1 += s[j][2] + s[j][3];
        }
        rs0 += __shfl_xor_sync(0xffffffffu, rs0, 1);
        rs0 += __shfl_xor_sync(0xffffffffu, rs0, 2);
        rs1 += __shfl_xor_sync(0xffffffffu, rs1, 1);
        rs1 += __shfl_xor_sync(0xffffffffu, rs1, 2);
        l0r = l0r * corr0 + rs0;
        l1r = l1r * corr1 + rs1;
        m0r = mn0; m1r = mn1;
        #pragma unroll
        for (int j = 0; j < 8; j++) {
            o[j][0] *= corr0; o[j][1] *= corr0;
            o[j][2] *= corr1; o[j][3] *= corr1;
        }

        // ---- O += P V (both single fp16) ----
        #pragma unroll
        for (int kt = 0; kt < 4; kt++) {
            uint32_t ph[4];
            ph[0] = pack_f16(s[2 * kt][0],     s[2 * kt][1]);
            ph[1] = pack_f16(s[2 * kt][2],     s[2 * kt][3]);
            ph[2] = pack_f16(s[2 * kt + 1][0], s[2 * kt + 1][1]);
            ph[3] = pack_f16(s[2 * kt + 1][2], s[2 * kt + 1][3]);
            #pragma unroll
            for (int dn = 0; dn < 4; dn++) {
                uint32_t a = so + (uint32_t)(ATILE + (kt * 16 + lra) * ATS +
                                             dn * 16 + kca) * 2;
                uint32_t v4[4];
                ldsm4t(v4, a);
                mma16816(o[2 * dn],     ph, v4[0], v4[1]);
                mma16816(o[2 * dn + 1], ph, v4[2], v4[3]);
            }
        }
    }

    // ---- epilogue: normalize and write single-fp16 O ----
    const float il0 = 1.0f / l0r, il1 = 1.0f / l1r;
    const int r0 = i0 + warp * 16 + (lane >> 2);
    #pragma unroll
    for (int j = 0; j < 8; j++) {
        int col = gcol + j * 8 + (lane & 3) * 2;
        *(uint32_t*)&Oh[(grow + r0) * CD + col] =
            pack_f16(o[j][0] * il0, o[j][1] * il0);
        *(uint32_t*)&Oh[(grow + r0 + 8) * CD + col] =
            pack_f16(o[j][2] * il1, o[j][3] * il1);
    }
}

// ---------------------------------------------------------------------------

extern "C" void kernel_launch(void* const* d_in, const int* in_sizes, int n_in,
                              void* d_out, int out_size) {
    const float* x  = (const float*)d_in[0];
    const float* Wq = (const float*)d_in[1];
    const float* Wk = (const float*)d_in[2];
    const float* Wv = (const float*)d_in[3];
    const float* Wo = (const float*)d_in[4];
    float* out = (float*)d_out;

    __half *xh, *qh, *kh, *vh, *oh, *wh;
    cudaGetSymbolAddress((void**)&xh, g_xh);
    cudaGetSymbolAddress((void**)&qh, g_qh);
    cudaGetSymbolAddress((void**)&kh, g_kh);
    cudaGetSymbolAddress((void**)&vh, g_vh);
    cudaGetSymbolAddress((void**)&oh, g_oh);
    cudaGetSymbolAddress((void**)&wh, g_wh);

    cudaFuncSetAttribute(gemm_f16<0>,
                         cudaFuncAttributeMaxDynamicSharedMemorySize, QSMEM);
    cudaFuncSetAttribute(gemm_f16<1>,
                         cudaFuncAttributeMaxDynamicSharedMemorySize, QSMEM);
    cudaFuncSetAttribute(attn_mma,
                         cudaFuncAttributeMaxDynamicSharedMemorySize, ATT_SMEM);

    const size_t CC = (size_t)CD * CD;
    const int n4x = MD * CD / 4;

    conv_kernel<<<n4x / 256, 256>>>(x, xh, n4x);
    conv4_kernel<<<4096, 256>>>(Wq, Wk, Wv, Wo, wh);

    gemm_f16<0><<<dim3(24, MD / 128), 256, QSMEM>>>(xh, wh, qh, kh, vh, nullptr);

    attn_mma<<<dim3(TD / 128, BD * NH), 256, ATT_SMEM>>>(qh, kh, vh, oh);

    gemm_f16<1><<<dim3(CD / 128, MD / 128), 256, QSMEM>>>(
        oh, wh + 3 * CC, nullptr, nullptr, nullptr, out);
}